// round 2
// baseline (speedup 1.0000x reference)
#include <cuda_runtime.h>
#include <cuda_bf16.h>
#include <math.h>

// ---------------- problem-size constants (fixed dataset) ----------------
#define MAXN 50000
#define MAXE 800000
#define MAXET (MAXN + MAXE)
#define MAXB 512

// ---------------- device scratch (static, no allocation) ----------------
__device__ float    g_xl[(size_t)MAXN * 128];
__device__ float    g_xr[(size_t)MAXN * 128];
__device__ float    g_e [(size_t)MAXET * 4];
__device__ unsigned g_lmax[(size_t)MAXN * 4];
__device__ float    g_den [(size_t)MAXN * 4];
__device__ float    g_hA[(size_t)MAXN * 128];
__device__ float    g_hB[(size_t)MAXN * 128];
__device__ int      g_src[MAXET];
__device__ int      g_dst[MAXET];
__device__ float    g_pool[MAXB * 32];
__device__ float    g_cnt[MAXB];

// ---------------- helpers ----------------
__device__ __forceinline__ unsigned f2u(float f) {
    unsigned u = __float_as_uint(f);
    return (u & 0x80000000u) ? ~u : (u | 0x80000000u);
}
__device__ __forceinline__ float u2f(unsigned u) {
    return __uint_as_float((u & 0x80000000u) ? (u ^ 0x80000000u) : ~u);
}

__global__ void zero_f(float* p, int n) {
    int i = blockIdx.x * blockDim.x + threadIdx.x;
    if (i < n) p[i] = 0.f;
}

// edge_index / batch are INT32: jax.random.randint(jnp.int64) silently yields
// int32 when x64 is disabled (JAX default).
__global__ void prep_edges(const int* __restrict__ ei, int E, int N) {
    int i = blockIdx.x * blockDim.x + threadIdx.x;
    int Etot = E + N;
    if (i >= Etot) return;
    if (i < E) {
        g_src[i] = ei[i];
        g_dst[i] = ei[E + i];
    } else {
        g_src[i] = i - E;
        g_dst[i] = i - E;
    }
}

// ---------------- GEMM: C[N,M] = A[N,128] @ W[128,M] + bias  (K fixed 128) ----------------
__global__ __launch_bounds__(256) void gemm128(
    const float* __restrict__ A, const float* __restrict__ W,
    const float* __restrict__ bias, float* __restrict__ C,
    int N, int M)
{
    __shared__ float As[16][64];
    __shared__ float Ws[16][64];
    const int t = threadIdx.x;
    const int row0 = blockIdx.y * 64;
    const int col0 = blockIdx.x * 64;
    const int tx = t & 15, ty = t >> 4;

    float acc[4][4];
#pragma unroll
    for (int i = 0; i < 4; i++)
#pragma unroll
        for (int j = 0; j < 4; j++) acc[i][j] = 0.f;

    for (int k0 = 0; k0 < 128; k0 += 16) {
#pragma unroll
        for (int i = 0; i < 4; i++) {
            int idx = t + i * 256;          // 0..1023
            int r = idx >> 4, c = idx & 15; // 64 rows x 16 k
            int gr = row0 + r;
            As[c][r] = (gr < N) ? A[(size_t)gr * 128 + k0 + c] : 0.f;
        }
#pragma unroll
        for (int i = 0; i < 4; i++) {
            int idx = t + i * 256;
            int kk = idx >> 6, cc = idx & 63; // 16 k x 64 cols
            int gc = col0 + cc;
            Ws[kk][cc] = (gc < M) ? W[(size_t)(k0 + kk) * M + gc] : 0.f;
        }
        __syncthreads();
#pragma unroll
        for (int kk = 0; kk < 16; kk++) {
            float4 a4 = *(const float4*)&As[kk][ty * 4];
            float4 w4 = *(const float4*)&Ws[kk][tx * 4];
            float a[4] = {a4.x, a4.y, a4.z, a4.w};
            float w[4] = {w4.x, w4.y, w4.z, w4.w};
#pragma unroll
            for (int i = 0; i < 4; i++)
#pragma unroll
                for (int j = 0; j < 4; j++) acc[i][j] += a[i] * w[j];
        }
        __syncthreads();
    }
#pragma unroll
    for (int i = 0; i < 4; i++) {
        int r = row0 + ty * 4 + i;
        if (r >= N) continue;
#pragma unroll
        for (int j = 0; j < 4; j++) {
            int c = col0 + tx * 4 + j;
            if (c < M) C[(size_t)r * M + c] = acc[i][j] + bias[c];
        }
    }
}

// ---------------- edge pass 1: logits + segment max ----------------
template <int H>
__global__ void edge_logits(const float* __restrict__ xl, const float* __restrict__ xr,
                            const float* __restrict__ att, float* __restrict__ elog,
                            unsigned* __restrict__ lmax, int Etot)
{
    int e = (blockIdx.x * blockDim.x + threadIdx.x) >> 5;
    int lane = threadIdx.x & 31;
    if (e >= Etot) return;
    int s = g_src[e], d = g_dst[e];
    const float* a = xl + (size_t)s * (H * 32);
    const float* b = xr + (size_t)d * (H * 32);
    float sum[H];
#pragma unroll
    for (int h = 0; h < H; h++) {
        float v = a[h * 32 + lane] + b[h * 32 + lane];
        v = v > 0.f ? v : 0.2f * v;                 // leaky_relu(0.2)
        float p = v * att[h * 32 + lane];
#pragma unroll
        for (int o = 16; o; o >>= 1) p += __shfl_xor_sync(0xffffffffu, p, o);
        sum[h] = p;
    }
#pragma unroll
    for (int h = 0; h < H; h++) {
        if (lane == h) {
            elog[(size_t)e * H + h] = sum[h];
            atomicMax(&lmax[(size_t)d * H + h], f2u(sum[h]));
        }
    }
}

// ---------------- edge pass 2: exp + segment sum ----------------
template <int H>
__global__ void edge_exp(float* __restrict__ elog, const unsigned* __restrict__ lmax,
                         float* __restrict__ den, int Etot)
{
    int t = blockIdx.x * blockDim.x + threadIdx.x;
    if (t >= Etot * H) return;
    int e = t / H;
    int h = t - e * H;
    int d = g_dst[e];
    float mx = u2f(lmax[(size_t)d * H + h]);
    float ex = __expf(elog[t] - mx);
    elog[t] = ex;
    atomicAdd(&den[(size_t)d * H + h], ex);
}

// ---------------- edge pass 3: weighted aggregation ----------------
template <int H>
__global__ void edge_agg(const float* __restrict__ xl, const float* __restrict__ elog,
                         const float* __restrict__ den, float* __restrict__ out, int Etot)
{
    int e = (blockIdx.x * blockDim.x + threadIdx.x) >> 5;
    int lane = threadIdx.x & 31;
    if (e >= Etot) return;
    int s = g_src[e], d = g_dst[e];
    float al = 0.f;
    if (lane < H) al = elog[(size_t)e * H + lane] / (den[(size_t)d * H + lane] + 1e-16f);
#pragma unroll
    for (int h = 0; h < H; h++) {
        float alpha = __shfl_sync(0xffffffffu, al, h);
        atomicAdd(&out[(size_t)d * (H * 32) + h * 32 + lane],
                  alpha * xl[(size_t)s * (H * 32) + h * 32 + lane]);
    }
}

// ---------------- bias + ELU ----------------
__global__ void bias_elu(float* __restrict__ io, const float* __restrict__ bias,
                         int total, int Dim)
{
    int i = blockIdx.x * blockDim.x + threadIdx.x;
    if (i >= total) return;
    float v = io[i] + bias[i % Dim];
    io[i] = v > 0.f ? v : expm1f(v);
}

// ---------------- graph mean pool (accumulate) ----------------
__global__ void pool_acc(const float* __restrict__ h, const int* __restrict__ batch, int N)
{
    int n = (blockIdx.x * blockDim.x + threadIdx.x) >> 5;
    int lane = threadIdx.x & 31;
    if (n >= N) return;
    int b = batch[n];
    atomicAdd(&g_pool[b * 32 + lane], h[(size_t)n * 32 + lane]);
    if (lane == 0) atomicAdd(&g_cnt[b], 1.f);
}

// ---------------- final MLP head: one warp per graph ----------------
__global__ void mlp_head(const float* __restrict__ meta,
                         const float* __restrict__ Wh1, const float* __restrict__ bh1,
                         const float* __restrict__ Wh2, const float* __restrict__ bh2,
                         float* __restrict__ out, int B, int metaDim)
{
    int g = (blockIdx.x * blockDim.x + threadIdx.x) >> 5;
    int lane = threadIdx.x & 31;
    if (g >= B) return;
    float cnt = fmaxf(g_cnt[g], 1.f);
    float acc = bh1[lane];
#pragma unroll 8
    for (int k = 0; k < 32; k++)
        acc += (g_pool[g * 32 + k] / cnt) * Wh1[k * 32 + lane];
    for (int k = 0; k < metaDim; k++)
        acc += meta[(size_t)g * metaDim + k] * Wh1[(32 + k) * 32 + lane];
    acc = fmaxf(acc, 0.f);
    float p = acc * Wh2[lane];
#pragma unroll
    for (int o = 16; o; o >>= 1) p += __shfl_xor_sync(0xffffffffu, p, o);
    if (lane == 0) out[g] = p + bh2[0];
}

// ---------------- host launcher ----------------
extern "C" void kernel_launch(void* const* d_in, const int* in_sizes, int n_in,
                              void* d_out, int out_size)
{
    const float* x     = (const float*)d_in[0];
    const int*   ei    = (const int*)d_in[1];    // int32 (JAX x64 disabled)
    const int*   batch = (const int*)d_in[2];    // int32
    const float* meta  = (const float*)d_in[3];
    const float* Wl[3]  = {(const float*)d_in[4],  (const float*)d_in[10], (const float*)d_in[16]};
    const float* bl[3]  = {(const float*)d_in[5],  (const float*)d_in[11], (const float*)d_in[17]};
    const float* Wr[3]  = {(const float*)d_in[6],  (const float*)d_in[12], (const float*)d_in[18]};
    const float* br[3]  = {(const float*)d_in[7],  (const float*)d_in[13], (const float*)d_in[19]};
    const float* att[3] = {(const float*)d_in[8],  (const float*)d_in[14], (const float*)d_in[20]};
    const float* bc[3]  = {(const float*)d_in[9],  (const float*)d_in[15], (const float*)d_in[21]};
    const float* Wh1 = (const float*)d_in[22];
    const float* bh1 = (const float*)d_in[23];
    const float* Wh2 = (const float*)d_in[24];
    const float* bh2 = (const float*)d_in[25];

    const int N = in_sizes[0] / 128;
    const int E = in_sizes[1] / 2;
    const int metaDim = 12;
    const int B = in_sizes[3] / metaDim;
    const int Etot = E + N;

    float *xl, *xr, *elog, *den, *hA, *hB, *pool, *cnt;
    unsigned* lmax;
    cudaGetSymbolAddress((void**)&xl,   g_xl);
    cudaGetSymbolAddress((void**)&xr,   g_xr);
    cudaGetSymbolAddress((void**)&elog, g_e);
    cudaGetSymbolAddress((void**)&lmax, g_lmax);
    cudaGetSymbolAddress((void**)&den,  g_den);
    cudaGetSymbolAddress((void**)&hA,   g_hA);
    cudaGetSymbolAddress((void**)&hB,   g_hB);
    cudaGetSymbolAddress((void**)&pool, g_pool);
    cudaGetSymbolAddress((void**)&cnt,  g_cnt);

    prep_edges<<<(Etot + 255) / 256, 256>>>(ei, E, N);

    const float* in = x;
    float* outBuf[3] = {hA, hB, hA};
    const int Hh[3] = {4, 4, 1};

    for (int li = 0; li < 3; li++) {
        const int H = Hh[li];
        const int HC = H * 32;

        dim3 ggrid((HC + 63) / 64, (N + 63) / 64);
        gemm128<<<ggrid, 256>>>(in, Wl[li], bl[li], xl, N, HC);
        gemm128<<<ggrid, 256>>>(in, Wr[li], br[li], xr, N, HC);

        zero_f<<<(N * H + 255) / 256, 256>>>((float*)lmax, N * H);
        zero_f<<<(N * H + 255) / 256, 256>>>(den, N * H);
        zero_f<<<(N * HC + 255) / 256, 256>>>(outBuf[li], N * HC);

        int warpGrid = (Etot * 32 + 255) / 256;
        if (H == 4) {
            edge_logits<4><<<warpGrid, 256>>>(xl, xr, att[li], elog, lmax, Etot);
            edge_exp<4><<<(Etot * 4 + 255) / 256, 256>>>(elog, lmax, den, Etot);
            edge_agg<4><<<warpGrid, 256>>>(xl, elog, den, outBuf[li], Etot);
        } else {
            edge_logits<1><<<warpGrid, 256>>>(xl, xr, att[li], elog, lmax, Etot);
            edge_exp<1><<<(Etot + 255) / 256, 256>>>(elog, lmax, den, Etot);
            edge_agg<1><<<warpGrid, 256>>>(xl, elog, den, outBuf[li], Etot);
        }
        bias_elu<<<(N * HC + 255) / 256, 256>>>(outBuf[li], bc[li], N * HC, HC);
        in = outBuf[li];
    }

    // global mean pool + MLP head
    zero_f<<<(B * 32 + 255) / 256, 256>>>(pool, B * 32);
    zero_f<<<(B + 255) / 256, 256>>>(cnt, B);
    pool_acc<<<(N * 32 + 255) / 256, 256>>>(outBuf[2], batch, N);
    mlp_head<<<(B * 32 + 255) / 256, 256>>>(meta, Wh1, bh1, Wh2, bh2,
                                            (float*)d_out, B, metaDim);
}

// round 3
// speedup vs baseline: 1.7008x; 1.7008x over previous
#include <cuda_runtime.h>
#include <cuda_bf16.h>
#include <math.h>

// ---------------- problem-size constants (fixed dataset) ----------------
#define MAXN 50000
#define MAXE 800000
#define MAXET (MAXN + MAXE)
#define MAXB 512

// ---------------- device scratch (static, no allocation) ----------------
__device__ float g_xl[(size_t)MAXN * 128];
__device__ float g_xr[(size_t)MAXN * 128];
__device__ float g_e [(size_t)MAXET * 4];   // per-edge logits / exp scratch
__device__ float g_hA[(size_t)MAXN * 128];
__device__ float g_hB[(size_t)MAXN * 128];
__device__ int   g_src[MAXET];
__device__ int   g_dst[MAXET];
__device__ int   g_deg[MAXN];
__device__ int   g_off[MAXN + 1];
__device__ int   g_pos[MAXN];
__device__ int   g_csr[MAXET];              // src ids sorted by dst
__device__ float g_pool[MAXB * 32];
__device__ float g_cnt[MAXB];

// ---------------- f32x2 packed-FMA helpers (sm_103a FFMA2 path) ----------------
__device__ __forceinline__ unsigned long long pk2(float x, float y) {
    unsigned long long r;
    asm("mov.b64 %0, {%1, %2};" : "=l"(r) : "f"(x), "f"(y));
    return r;
}
__device__ __forceinline__ void upk2(unsigned long long v, float& x, float& y) {
    asm("mov.b64 {%0, %1}, %2;" : "=f"(x), "=f"(y) : "l"(v));
}
__device__ __forceinline__ unsigned long long ffma2(
    unsigned long long a, unsigned long long b, unsigned long long c) {
    unsigned long long d;
    asm("fma.rn.f32x2 %0, %1, %2, %3;" : "=l"(d) : "l"(a), "l"(b), "l"(c));
    return d;
}

// ---------------- small utility kernels ----------------
__global__ void zero_f(float* p, int n) {
    int i = blockIdx.x * blockDim.x + threadIdx.x;
    if (i < n) p[i] = 0.f;
}
__global__ void zero_i(int* p, int n) {
    int i = blockIdx.x * blockDim.x + threadIdx.x;
    if (i < n) p[i] = 0;
}

// edge_index / batch are INT32 (JAX x64 disabled).
__global__ void prep_edges(const int* __restrict__ ei, int E, int N) {
    int i = blockIdx.x * blockDim.x + threadIdx.x;
    int Etot = E + N;
    if (i >= Etot) return;
    int s, d;
    if (i < E) { s = ei[i]; d = ei[E + i]; }
    else       { s = i - E; d = i - E; }
    g_src[i] = s;
    g_dst[i] = d;
    atomicAdd(&g_deg[d], 1);
}

// single-block exclusive scan of g_deg -> g_off  (N up to 50000)
__global__ void scan_deg(int N) {
    __shared__ int wsum[32];
    __shared__ int carry;
    int tid = threadIdx.x, lane = tid & 31, wid = tid >> 5;
    if (tid == 0) { carry = 0; g_off[0] = 0; }
    __syncthreads();
    for (int base = 0; base < N; base += 1024) {
        int i = base + tid;
        int x = (i < N) ? g_deg[i] : 0;
#pragma unroll
        for (int o = 1; o < 32; o <<= 1) {
            int y = __shfl_up_sync(0xffffffffu, x, o);
            if (lane >= o) x += y;
        }
        if (lane == 31) wsum[wid] = x;
        __syncthreads();
        if (wid == 0) {
            int s = wsum[lane];
#pragma unroll
            for (int o = 1; o < 32; o <<= 1) {
                int y = __shfl_up_sync(0xffffffffu, s, o);
                if (lane >= o) s += y;
            }
            wsum[lane] = s;
        }
        __syncthreads();
        int incl = x + (wid ? wsum[wid - 1] : 0) + carry;
        if (i < N) g_off[i + 1] = incl;
        __syncthreads();
        if (tid == 1023) carry = incl;
        __syncthreads();
    }
}

__global__ void scatter_edges(int Etot) {
    int i = blockIdx.x * blockDim.x + threadIdx.x;
    if (i >= Etot) return;
    int d = g_dst[i];
    int p = atomicAdd(&g_pos[d], 1);
    g_csr[g_off[d] + p] = g_src[i];
}

// ---------------- big GEMM: C[N,128] = A[N,128] @ W[128,128] + bias ----------------
// 128-row x 128-col tile per block, K chunked by 16, double-buffered,
// packed f32x2 FMA (row-pair accumulators).
__global__ __launch_bounds__(256) void gemm_f128(
    const float* __restrict__ A, const float* __restrict__ W,
    const float* __restrict__ bias, float* __restrict__ C, int N)
{
    __shared__ float Ast[2][16][130];   // [buf][k][row] transposed, padded
    __shared__ float Wst[2][16][128];   // [buf][k][col]
    const int t = threadIdx.x;
    const int row0 = blockIdx.x * 128;
    const int tx = t & 15, ty = t >> 4;   // 16x16 thread grid
    const int r0 = ty * 8, c0 = tx * 8;

    unsigned long long acc[4][8];
#pragma unroll
    for (int p = 0; p < 4; p++)
#pragma unroll
        for (int j = 0; j < 8; j++) acc[p][j] = pk2(0.f, 0.f);

    // per-thread load mapping
    const int ar[2]  = {(t + 0) >> 2,   (t + 256) >> 2};    // A row within tile
    const int ac4[2] = {(t + 0) & 3,    (t + 256) & 3};     // A float4-col within chunk
    const int wk[2]  = {(t + 0) >> 5,   (t + 256) >> 5};    // W k within chunk
    const int wc4[2] = {(t + 0) & 31,   (t + 256) & 31};    // W float4-col

    float4 aR[2], wR[2];

    // ---- load chunk 0 ----
#pragma unroll
    for (int i = 0; i < 2; i++) {
        int gr = row0 + ar[i];
        aR[i] = (gr < N) ? *(const float4*)&A[(size_t)gr * 128 + ac4[i] * 4]
                         : make_float4(0.f, 0.f, 0.f, 0.f);
        wR[i] = *(const float4*)&W[(size_t)wk[i] * 128 + wc4[i] * 4];
    }
#pragma unroll
    for (int i = 0; i < 2; i++) {
        Ast[0][ac4[i] * 4 + 0][ar[i]] = aR[i].x;
        Ast[0][ac4[i] * 4 + 1][ar[i]] = aR[i].y;
        Ast[0][ac4[i] * 4 + 2][ar[i]] = aR[i].z;
        Ast[0][ac4[i] * 4 + 3][ar[i]] = aR[i].w;
        *(float4*)&Wst[0][wk[i]][wc4[i] * 4] = wR[i];
    }
    __syncthreads();

    for (int kc = 0; kc < 8; kc++) {
        int b = kc & 1;
        if (kc < 7) {
#pragma unroll
            for (int i = 0; i < 2; i++) {
                int gr = row0 + ar[i];
                aR[i] = (gr < N) ? *(const float4*)&A[(size_t)gr * 128 + (kc + 1) * 16 + ac4[i] * 4]
                                 : make_float4(0.f, 0.f, 0.f, 0.f);
                wR[i] = *(const float4*)&W[(size_t)((kc + 1) * 16 + wk[i]) * 128 + wc4[i] * 4];
            }
        }
#pragma unroll
        for (int k = 0; k < 16; k++) {
            unsigned long long av[4];
#pragma unroll
            for (int p = 0; p < 4; p++) {
                float2 a2 = *(const float2*)&Ast[b][k][r0 + p * 2];
                av[p] = pk2(a2.x, a2.y);
            }
            float4 w0 = *(const float4*)&Wst[b][k][c0];
            float4 w1 = *(const float4*)&Wst[b][k][c0 + 4];
            unsigned long long wd[8];
            wd[0] = pk2(w0.x, w0.x); wd[1] = pk2(w0.y, w0.y);
            wd[2] = pk2(w0.z, w0.z); wd[3] = pk2(w0.w, w0.w);
            wd[4] = pk2(w1.x, w1.x); wd[5] = pk2(w1.y, w1.y);
            wd[6] = pk2(w1.z, w1.z); wd[7] = pk2(w1.w, w1.w);
#pragma unroll
            for (int p = 0; p < 4; p++)
#pragma unroll
                for (int j = 0; j < 8; j++)
                    acc[p][j] = ffma2(av[p], wd[j], acc[p][j]);
        }
        if (kc < 7) {
            int nb = b ^ 1;
#pragma unroll
            for (int i = 0; i < 2; i++) {
                Ast[nb][ac4[i] * 4 + 0][ar[i]] = aR[i].x;
                Ast[nb][ac4[i] * 4 + 1][ar[i]] = aR[i].y;
                Ast[nb][ac4[i] * 4 + 2][ar[i]] = aR[i].z;
                Ast[nb][ac4[i] * 4 + 3][ar[i]] = aR[i].w;
                *(float4*)&Wst[nb][wk[i]][wc4[i] * 4] = wR[i];
            }
            __syncthreads();
        }
    }

    // ---- epilogue ----
#pragma unroll
    for (int p = 0; p < 4; p++) {
        int rA = row0 + r0 + p * 2;
        int rB = rA + 1;
#pragma unroll
        for (int j = 0; j < 8; j++) {
            float lo, hi;
            upk2(acc[p][j], lo, hi);
            int c = c0 + j;
            if (rA < N) C[(size_t)rA * 128 + c] = lo + bias[c];
            if (rB < N) C[(size_t)rB * 128 + c] = hi + bias[c];
        }
    }
}

// ---------------- small GEMM (M=32): C[N,M] = A[N,128] @ W[128,M] + bias ----------------
__global__ __launch_bounds__(256) void gemm128(
    const float* __restrict__ A, const float* __restrict__ W,
    const float* __restrict__ bias, float* __restrict__ C,
    int N, int M)
{
    __shared__ float As[16][64];
    __shared__ float Ws[16][64];
    const int t = threadIdx.x;
    const int row0 = blockIdx.y * 64;
    const int col0 = blockIdx.x * 64;
    const int tx = t & 15, ty = t >> 4;

    float acc[4][4];
#pragma unroll
    for (int i = 0; i < 4; i++)
#pragma unroll
        for (int j = 0; j < 4; j++) acc[i][j] = 0.f;

    for (int k0 = 0; k0 < 128; k0 += 16) {
#pragma unroll
        for (int i = 0; i < 4; i++) {
            int idx = t + i * 256;
            int r = idx >> 4, c = idx & 15;
            int gr = row0 + r;
            As[c][r] = (gr < N) ? A[(size_t)gr * 128 + k0 + c] : 0.f;
        }
#pragma unroll
        for (int i = 0; i < 4; i++) {
            int idx = t + i * 256;
            int kk = idx >> 6, cc = idx & 63;
            int gc = col0 + cc;
            Ws[kk][cc] = (gc < M) ? W[(size_t)(k0 + kk) * M + gc] : 0.f;
        }
        __syncthreads();
#pragma unroll
        for (int kk = 0; kk < 16; kk++) {
            float4 a4 = *(const float4*)&As[kk][ty * 4];
            float4 w4 = *(const float4*)&Ws[kk][tx * 4];
            float a[4] = {a4.x, a4.y, a4.z, a4.w};
            float w[4] = {w4.x, w4.y, w4.z, w4.w};
#pragma unroll
            for (int i = 0; i < 4; i++)
#pragma unroll
                for (int j = 0; j < 4; j++) acc[i][j] += a[i] * w[j];
        }
        __syncthreads();
    }
#pragma unroll
    for (int i = 0; i < 4; i++) {
        int r = row0 + ty * 4 + i;
        if (r >= N) continue;
#pragma unroll
        for (int j = 0; j < 4; j++) {
            int c = col0 + tx * 4 + j;
            if (c < M) C[(size_t)r * M + c] = acc[i][j] + bias[c];
        }
    }
}

// ---------------- fused GATv2 attention: one warp per destination node ----------------
// CSR (sorted by dst) -> no atomics. Two sweeps over in-edges:
//   sweep 1: logits (store per-edge) + running max
//   sweep 2: exp, denominator, weighted aggregation of xl[src]
// Epilogue fuses bias + ELU.
template <int H>
__global__ void gat_fused(const float* __restrict__ xl, const float* __restrict__ xr,
                          const float* __restrict__ att, const float* __restrict__ bias,
                          float* __restrict__ elog, float* __restrict__ out, int N)
{
    const int HC = H * 32;
    int w = (blockIdx.x * blockDim.x + threadIdx.x) >> 5;
    if (w >= N) return;
    int lane = threadIdx.x & 31;

    float xrv[H], attv[H], mx[H];
#pragma unroll
    for (int h = 0; h < H; h++) {
        xrv[h]  = xr[(size_t)w * HC + h * 32 + lane];
        attv[h] = att[h * 32 + lane];
        mx[h]   = -1e30f;
    }
    int j0 = g_off[w], j1 = g_off[w + 1];

    for (int j = j0; j < j1; j++) {
        int s = g_csr[j];
        const float* xs = xl + (size_t)s * HC;
#pragma unroll
        for (int h = 0; h < H; h++) {
            float v = xs[h * 32 + lane] + xrv[h];
            v = v > 0.f ? v : 0.2f * v;             // leaky_relu(0.2)
            float p = v * attv[h];
#pragma unroll
            for (int o = 16; o; o >>= 1) p += __shfl_xor_sync(0xffffffffu, p, o);
            if (lane == h) elog[(size_t)j * H + h] = p;
            mx[h] = fmaxf(mx[h], p);
        }
    }

    float acc[H], den[H];
#pragma unroll
    for (int h = 0; h < H; h++) { acc[h] = 0.f; den[h] = 0.f; }

    for (int j = j0; j < j1; j++) {
        int s = g_csr[j];
        const float* xs = xl + (size_t)s * HC;
#pragma unroll
        for (int h = 0; h < H; h++) {
            float e = __expf(elog[(size_t)j * H + h] - mx[h]);
            den[h] += e;
            acc[h] += e * xs[h * 32 + lane];
        }
    }

#pragma unroll
    for (int h = 0; h < H; h++) {
        float o = acc[h] / (den[h] + 1e-16f) + bias[h * 32 + lane];
        o = o > 0.f ? o : expm1f(o);                // ELU
        out[(size_t)w * HC + h * 32 + lane] = o;
    }
}

// ---------------- graph mean pool (accumulate) ----------------
__global__ void pool_acc(const float* __restrict__ h, const int* __restrict__ batch, int N)
{
    int n = (blockIdx.x * blockDim.x + threadIdx.x) >> 5;
    int lane = threadIdx.x & 31;
    if (n >= N) return;
    int b = batch[n];
    atomicAdd(&g_pool[b * 32 + lane], h[(size_t)n * 32 + lane]);
    if (lane == 0) atomicAdd(&g_cnt[b], 1.f);
}

// ---------------- final MLP head: one warp per graph ----------------
__global__ void mlp_head(const float* __restrict__ meta,
                         const float* __restrict__ Wh1, const float* __restrict__ bh1,
                         const float* __restrict__ Wh2, const float* __restrict__ bh2,
                         float* __restrict__ out, int B, int metaDim)
{
    int g = (blockIdx.x * blockDim.x + threadIdx.x) >> 5;
    int lane = threadIdx.x & 31;
    if (g >= B) return;
    float cnt = fmaxf(g_cnt[g], 1.f);
    float acc = bh1[lane];
#pragma unroll 8
    for (int k = 0; k < 32; k++)
        acc += (g_pool[g * 32 + k] / cnt) * Wh1[k * 32 + lane];
    for (int k = 0; k < metaDim; k++)
        acc += meta[(size_t)g * metaDim + k] * Wh1[(32 + k) * 32 + lane];
    acc = fmaxf(acc, 0.f);
    float p = acc * Wh2[lane];
#pragma unroll
    for (int o = 16; o; o >>= 1) p += __shfl_xor_sync(0xffffffffu, p, o);
    if (lane == 0) out[g] = p + bh2[0];
}

// ---------------- host launcher ----------------
extern "C" void kernel_launch(void* const* d_in, const int* in_sizes, int n_in,
                              void* d_out, int out_size)
{
    const float* x     = (const float*)d_in[0];
    const int*   ei    = (const int*)d_in[1];    // int32 (JAX x64 disabled)
    const int*   batch = (const int*)d_in[2];    // int32
    const float* meta  = (const float*)d_in[3];
    const float* Wl[3]  = {(const float*)d_in[4],  (const float*)d_in[10], (const float*)d_in[16]};
    const float* bl[3]  = {(const float*)d_in[5],  (const float*)d_in[11], (const float*)d_in[17]};
    const float* Wr[3]  = {(const float*)d_in[6],  (const float*)d_in[12], (const float*)d_in[18]};
    const float* br[3]  = {(const float*)d_in[7],  (const float*)d_in[13], (const float*)d_in[19]};
    const float* att[3] = {(const float*)d_in[8],  (const float*)d_in[14], (const float*)d_in[20]};
    const float* bc[3]  = {(const float*)d_in[9],  (const float*)d_in[15], (const float*)d_in[21]};
    const float* Wh1 = (const float*)d_in[22];
    const float* bh1 = (const float*)d_in[23];
    const float* Wh2 = (const float*)d_in[24];
    const float* bh2 = (const float*)d_in[25];

    const int N = in_sizes[0] / 128;
    const int E = in_sizes[1] / 2;
    const int metaDim = 12;
    const int B = in_sizes[3] / metaDim;
    const int Etot = E + N;

    float *xl, *xr, *elog, *hA, *hB, *pool, *cnt;
    int *deg, *pos;
    cudaGetSymbolAddress((void**)&xl,   g_xl);
    cudaGetSymbolAddress((void**)&xr,   g_xr);
    cudaGetSymbolAddress((void**)&elog, g_e);
    cudaGetSymbolAddress((void**)&hA,   g_hA);
    cudaGetSymbolAddress((void**)&hB,   g_hB);
    cudaGetSymbolAddress((void**)&pool, g_pool);
    cudaGetSymbolAddress((void**)&cnt,  g_cnt);
    cudaGetSymbolAddress((void**)&deg,  g_deg);
    cudaGetSymbolAddress((void**)&pos,  g_pos);

    // ---- build CSR (dst-sorted) ----
    zero_i<<<(N + 255) / 256, 256>>>(deg, N);
    zero_i<<<(N + 255) / 256, 256>>>(pos, N);
    prep_edges<<<(Etot + 255) / 256, 256>>>(ei, E, N);
    scan_deg<<<1, 1024>>>(N);
    scatter_edges<<<(Etot + 255) / 256, 256>>>(Etot);

    const int warpGrid = (N * 32 + 255) / 256;

    // ---- layer 0 (H=4) ----
    gemm_f128<<<(N + 127) / 128, 256>>>(x, Wl[0], bl[0], xl, N);
    gemm_f128<<<(N + 127) / 128, 256>>>(x, Wr[0], br[0], xr, N);
    gat_fused<4><<<warpGrid, 256>>>(xl, xr, att[0], bc[0], elog, hA, N);

    // ---- layer 1 (H=4) ----
    gemm_f128<<<(N + 127) / 128, 256>>>(hA, Wl[1], bl[1], xl, N);
    gemm_f128<<<(N + 127) / 128, 256>>>(hA, Wr[1], br[1], xr, N);
    gat_fused<4><<<warpGrid, 256>>>(xl, xr, att[1], bc[1], elog, hB, N);

    // ---- layer 2 (H=1, concat=False is identity for single head) ----
    {
        dim3 g2(1, (N + 63) / 64);
        gemm128<<<g2, 256>>>(hB, Wl[2], bl[2], xl, N, 32);
        gemm128<<<g2, 256>>>(hB, Wr[2], br[2], xr, N, 32);
    }
    gat_fused<1><<<warpGrid, 256>>>(xl, xr, att[2], bc[2], elog, hA, N);

    // ---- global mean pool + MLP head ----
    zero_f<<<(B * 32 + 255) / 256, 256>>>(pool, B * 32);
    zero_f<<<(B + 255) / 256, 256>>>(cnt, B);
    pool_acc<<<(N * 32 + 255) / 256, 256>>>(hA, batch, N);
    mlp_head<<<(B * 32 + 255) / 256, 256>>>(meta, Wh1, bh1, Wh2, bh2,
                                            (float*)d_out, B, metaDim);
}

// round 5
// speedup vs baseline: 1.8879x; 1.1100x over previous
#include <cuda_runtime.h>
#include <cuda_bf16.h>
#include <math.h>

// ---------------- problem-size constants (fixed dataset) ----------------
#define MAXN 50000
#define MAXE 800000
#define MAXET (MAXN + MAXE)
#define MAXB 512

// ---------------- device scratch (static, no allocation) ----------------
__device__ float g_xl[(size_t)MAXN * 128];
__device__ float g_xr[(size_t)MAXN * 128];
__device__ float g_hA[(size_t)MAXN * 128];
__device__ float g_hB[(size_t)MAXN * 128];
__device__ int   g_src[MAXET];
__device__ int   g_dst[MAXET];
__device__ int   g_deg[MAXN];
__device__ int   g_off[MAXN + 1];
__device__ int   g_pos[MAXN];
__device__ int   g_csr[MAXET];              // src ids sorted by dst
__device__ int   g_bsum[64];                // per-block sums for scan
__device__ float g_pool[MAXB * 32];
__device__ float g_cnt[MAXB];

// ---------------- f32x2 packed-FMA helpers (sm_103a FFMA2 path) ----------------
__device__ __forceinline__ unsigned long long pk2(float x, float y) {
    unsigned long long r;
    asm("mov.b64 %0, {%1, %2};" : "=l"(r) : "f"(x), "f"(y));
    return r;
}
__device__ __forceinline__ void upk2(unsigned long long v, float& x, float& y) {
    asm("mov.b64 {%0, %1}, %2;" : "=f"(x), "=f"(y) : "l"(v));
}
__device__ __forceinline__ unsigned long long ffma2(
    unsigned long long a, unsigned long long b, unsigned long long c) {
    unsigned long long d;
    asm("fma.rn.f32x2 %0, %1, %2, %3;" : "=l"(d) : "l"(a), "l"(b), "l"(c));
    return d;
}

// warp-wide float sum (shfl butterfly; redux.f32 is NOT supported on sm_103)
__device__ __forceinline__ float warp_sum(float v) {
#pragma unroll
    for (int o = 16; o; o >>= 1) v += __shfl_xor_sync(0xffffffffu, v, o);
    return v;
}

// ---------------- small utility kernels ----------------
__global__ void zero_f(float* p, int n) {
    int i = blockIdx.x * blockDim.x + threadIdx.x;
    if (i < n) p[i] = 0.f;
}
__global__ void zero_i(int* p, int n) {
    int i = blockIdx.x * blockDim.x + threadIdx.x;
    if (i < n) p[i] = 0;
}

// edge_index / batch are INT32 (JAX x64 disabled).
__global__ void prep_edges(const int* __restrict__ ei, int E, int N) {
    int i = blockIdx.x * blockDim.x + threadIdx.x;
    int Etot = E + N;
    if (i >= Etot) return;
    int s, d;
    if (i < E) { s = ei[i]; d = ei[E + i]; }
    else       { s = i - E; d = i - E; }
    g_src[i] = s;
    g_dst[i] = d;
    atomicAdd(&g_deg[d], 1);
}

// ---------------- multi-block scan of g_deg -> g_off ----------------
__global__ void scan_local(int N) {
    __shared__ int wsum[32];
    int b = blockIdx.x, tid = threadIdx.x, lane = tid & 31, wid = tid >> 5;
    int i = b * 1024 + tid;
    int x = (i < N) ? g_deg[i] : 0;
#pragma unroll
    for (int o = 1; o < 32; o <<= 1) {
        int y = __shfl_up_sync(0xffffffffu, x, o);
        if (lane >= o) x += y;
    }
    if (lane == 31) wsum[wid] = x;
    __syncthreads();
    if (wid == 0) {
        int s = wsum[lane];
#pragma unroll
        for (int o = 1; o < 32; o <<= 1) {
            int y = __shfl_up_sync(0xffffffffu, s, o);
            if (lane >= o) s += y;
        }
        wsum[lane] = s;
    }
    __syncthreads();
    int incl = x + (wid ? wsum[wid - 1] : 0);
    if (i < N) g_off[i + 1] = incl;
    if (tid == 1023) g_bsum[b] = incl;
}

__global__ void scan_tops(int nb) {
    __shared__ int s[64];
    int tid = threadIdx.x;
    if (tid < nb) s[tid] = g_bsum[tid];
    __syncthreads();
    if (tid == 0) {
        int a = 0;
        for (int i = 0; i < nb; i++) { int t = s[i]; s[i] = a; a += t; }
    }
    __syncthreads();
    if (tid < nb) g_bsum[tid] = s[tid];
}

__global__ void scan_add(int N) {
    int i = blockIdx.x * blockDim.x + threadIdx.x;
    if (i == 0) g_off[0] = 0;
    if (i < N) {
        g_off[i + 1] += g_bsum[i >> 10];
        g_pos[i] = 0;
    }
}

__global__ void scatter_edges(int Etot) {
    int i = blockIdx.x * blockDim.x + threadIdx.x;
    if (i >= Etot) return;
    int d = g_dst[i];
    int p = atomicAdd(&g_pos[d], 1);
    g_csr[g_off[d] + p] = g_src[i];
}

// ---------------- big GEMM: C[N,128] = A[N,128] @ W[128,128] + bias ----------------
__global__ __launch_bounds__(256) void gemm_f128(
    const float* __restrict__ A, const float* __restrict__ W,
    const float* __restrict__ bias, float* __restrict__ C, int N)
{
    __shared__ float Ast[2][16][130];   // [buf][k][row] transposed, padded
    __shared__ float Wst[2][16][128];   // [buf][k][col]
    const int t = threadIdx.x;
    const int row0 = blockIdx.x * 128;
    const int tx = t & 15, ty = t >> 4;   // 16x16 thread grid
    const int r0 = ty * 8, c0 = tx * 8;

    unsigned long long acc[4][8];
#pragma unroll
    for (int p = 0; p < 4; p++)
#pragma unroll
        for (int j = 0; j < 8; j++) acc[p][j] = pk2(0.f, 0.f);

    const int ar[2]  = {(t + 0) >> 2,   (t + 256) >> 2};
    const int ac4[2] = {(t + 0) & 3,    (t + 256) & 3};
    const int wk[2]  = {(t + 0) >> 5,   (t + 256) >> 5};
    const int wc4[2] = {(t + 0) & 31,   (t + 256) & 31};

    float4 aR[2], wR[2];

#pragma unroll
    for (int i = 0; i < 2; i++) {
        int gr = row0 + ar[i];
        aR[i] = (gr < N) ? *(const float4*)&A[(size_t)gr * 128 + ac4[i] * 4]
                         : make_float4(0.f, 0.f, 0.f, 0.f);
        wR[i] = *(const float4*)&W[(size_t)wk[i] * 128 + wc4[i] * 4];
    }
#pragma unroll
    for (int i = 0; i < 2; i++) {
        Ast[0][ac4[i] * 4 + 0][ar[i]] = aR[i].x;
        Ast[0][ac4[i] * 4 + 1][ar[i]] = aR[i].y;
        Ast[0][ac4[i] * 4 + 2][ar[i]] = aR[i].z;
        Ast[0][ac4[i] * 4 + 3][ar[i]] = aR[i].w;
        *(float4*)&Wst[0][wk[i]][wc4[i] * 4] = wR[i];
    }
    __syncthreads();

    for (int kc = 0; kc < 8; kc++) {
        int b = kc & 1;
        if (kc < 7) {
#pragma unroll
            for (int i = 0; i < 2; i++) {
                int gr = row0 + ar[i];
                aR[i] = (gr < N) ? *(const float4*)&A[(size_t)gr * 128 + (kc + 1) * 16 + ac4[i] * 4]
                                 : make_float4(0.f, 0.f, 0.f, 0.f);
                wR[i] = *(const float4*)&W[(size_t)((kc + 1) * 16 + wk[i]) * 128 + wc4[i] * 4];
            }
        }
#pragma unroll
        for (int k = 0; k < 16; k++) {
            unsigned long long av[4];
#pragma unroll
            for (int p = 0; p < 4; p++) {
                float2 a2 = *(const float2*)&Ast[b][k][r0 + p * 2];
                av[p] = pk2(a2.x, a2.y);
            }
            float4 w0 = *(const float4*)&Wst[b][k][c0];
            float4 w1 = *(const float4*)&Wst[b][k][c0 + 4];
            unsigned long long wd[8];
            wd[0] = pk2(w0.x, w0.x); wd[1] = pk2(w0.y, w0.y);
            wd[2] = pk2(w0.z, w0.z); wd[3] = pk2(w0.w, w0.w);
            wd[4] = pk2(w1.x, w1.x); wd[5] = pk2(w1.y, w1.y);
            wd[6] = pk2(w1.z, w1.z); wd[7] = pk2(w1.w, w1.w);
#pragma unroll
            for (int p = 0; p < 4; p++)
#pragma unroll
                for (int j = 0; j < 8; j++)
                    acc[p][j] = ffma2(av[p], wd[j], acc[p][j]);
        }
        if (kc < 7) {
            int nb = b ^ 1;
#pragma unroll
            for (int i = 0; i < 2; i++) {
                Ast[nb][ac4[i] * 4 + 0][ar[i]] = aR[i].x;
                Ast[nb][ac4[i] * 4 + 1][ar[i]] = aR[i].y;
                Ast[nb][ac4[i] * 4 + 2][ar[i]] = aR[i].z;
                Ast[nb][ac4[i] * 4 + 3][ar[i]] = aR[i].w;
                *(float4*)&Wst[nb][wk[i]][wc4[i] * 4] = wR[i];
            }
            __syncthreads();
        }
    }

#pragma unroll
    for (int p = 0; p < 4; p++) {
        int rA = row0 + r0 + p * 2;
        int rB = rA + 1;
#pragma unroll
        for (int j = 0; j < 8; j++) {
            float lo, hi;
            upk2(acc[p][j], lo, hi);
            int c = c0 + j;
            if (rA < N) C[(size_t)rA * 128 + c] = lo + bias[c];
            if (rB < N) C[(size_t)rB * 128 + c] = hi + bias[c];
        }
    }
}

// ---------------- small GEMM (M=32): C[N,M] = A[N,128] @ W[128,M] + bias ----------------
__global__ __launch_bounds__(256) void gemm128(
    const float* __restrict__ A, const float* __restrict__ W,
    const float* __restrict__ bias, float* __restrict__ C,
    int N, int M)
{
    __shared__ float As[16][64];
    __shared__ float Ws[16][64];
    const int t = threadIdx.x;
    const int row0 = blockIdx.y * 64;
    const int col0 = blockIdx.x * 64;
    const int tx = t & 15, ty = t >> 4;

    float acc[4][4];
#pragma unroll
    for (int i = 0; i < 4; i++)
#pragma unroll
        for (int j = 0; j < 4; j++) acc[i][j] = 0.f;

    for (int k0 = 0; k0 < 128; k0 += 16) {
#pragma unroll
        for (int i = 0; i < 4; i++) {
            int idx = t + i * 256;
            int r = idx >> 4, c = idx & 15;
            int gr = row0 + r;
            As[c][r] = (gr < N) ? A[(size_t)gr * 128 + k0 + c] : 0.f;
        }
#pragma unroll
        for (int i = 0; i < 4; i++) {
            int idx = t + i * 256;
            int kk = idx >> 6, cc = idx & 63;
            int gc = col0 + cc;
            Ws[kk][cc] = (gc < M) ? W[(size_t)(k0 + kk) * M + gc] : 0.f;
        }
        __syncthreads();
#pragma unroll
        for (int kk = 0; kk < 16; kk++) {
            float4 a4 = *(const float4*)&As[kk][ty * 4];
            float4 w4 = *(const float4*)&Ws[kk][tx * 4];
            float a[4] = {a4.x, a4.y, a4.z, a4.w};
            float w[4] = {w4.x, w4.y, w4.z, w4.w};
#pragma unroll
            for (int i = 0; i < 4; i++)
#pragma unroll
                for (int j = 0; j < 4; j++) acc[i][j] += a[i] * w[j];
        }
        __syncthreads();
    }
#pragma unroll
    for (int i = 0; i < 4; i++) {
        int r = row0 + ty * 4 + i;
        if (r >= N) continue;
#pragma unroll
        for (int j = 0; j < 4; j++) {
            int c = col0 + tx * 4 + j;
            if (c < M) C[(size_t)r * M + c] = acc[i][j] + bias[c];
        }
    }
}

// ---------------- fused GATv2 attention: one warp per destination node ----------------
// Single sweep with online softmax (rescale on new max). Software-pipelined:
// next edge's src row is loaded while the current edge is processed.
template <int H>
__global__ void gat_fused(const float* __restrict__ xl, const float* __restrict__ xr,
                          const float* __restrict__ att, const float* __restrict__ bias,
                          float* __restrict__ out, int N)
{
    const int HC = H * 32;
    int w = (blockIdx.x * blockDim.x + threadIdx.x) >> 5;
    if (w >= N) return;
    int lane = threadIdx.x & 31;

    float xrv[H], attv[H], mx[H], den[H], acc[H];
#pragma unroll
    for (int h = 0; h < H; h++) {
        xrv[h]  = xr[(size_t)w * HC + h * 32 + lane];
        attv[h] = att[h * 32 + lane];
        mx[h] = -1e30f; den[h] = 0.f; acc[h] = 0.f;
    }
    const int j0 = g_off[w], j1 = g_off[w + 1];

    int s = g_csr[j0];
    float v[H];
#pragma unroll
    for (int h = 0; h < H; h++) v[h] = xl[(size_t)s * HC + h * 32 + lane];

    for (int j = j0; j < j1; j++) {
        // prefetch next edge's src row (overlaps with compute below)
        int jn = (j + 1 < j1) ? j + 1 : j;
        int sn = g_csr[jn];
        float vn[H];
#pragma unroll
        for (int h = 0; h < H; h++) vn[h] = xl[(size_t)sn * HC + h * 32 + lane];

        float p[H];
#pragma unroll
        for (int h = 0; h < H; h++) {
            float t = v[h] + xrv[h];
            t = t > 0.f ? t : 0.2f * t;             // leaky_relu(0.2)
            p[h] = warp_sum(t * attv[h]);
        }
#pragma unroll
        for (int h = 0; h < H; h++) {
            if (p[h] > mx[h]) {                     // warp-uniform branch
                float sc = __expf(mx[h] - p[h]);    // first iter: exp(-huge)=0
                den[h] *= sc; acc[h] *= sc; mx[h] = p[h];
            }
            float e = __expf(p[h] - mx[h]);
            den[h] += e;
            acc[h] += e * v[h];
        }
#pragma unroll
        for (int h = 0; h < H; h++) v[h] = vn[h];
    }

#pragma unroll
    for (int h = 0; h < H; h++) {
        float o = acc[h] / (den[h] + 1e-16f) + bias[h * 32 + lane];
        o = o > 0.f ? o : expm1f(o);                // ELU
        out[(size_t)w * HC + h * 32 + lane] = o;
    }
}

// ---------------- graph mean pool (accumulate) ----------------
__global__ void pool_acc(const float* __restrict__ h, const int* __restrict__ batch, int N)
{
    int n = (blockIdx.x * blockDim.x + threadIdx.x) >> 5;
    int lane = threadIdx.x & 31;
    if (n >= N) return;
    int b = batch[n];
    atomicAdd(&g_pool[b * 32 + lane], h[(size_t)n * 32 + lane]);
    if (lane == 0) atomicAdd(&g_cnt[b], 1.f);
}

// ---------------- final MLP head: one warp per graph ----------------
__global__ void mlp_head(const float* __restrict__ meta,
                         const float* __restrict__ Wh1, const float* __restrict__ bh1,
                         const float* __restrict__ Wh2, const float* __restrict__ bh2,
                         float* __restrict__ out, int B, int metaDim)
{
    int g = (blockIdx.x * blockDim.x + threadIdx.x) >> 5;
    int lane = threadIdx.x & 31;
    if (g >= B) return;
    float cnt = fmaxf(g_cnt[g], 1.f);
    float acc = bh1[lane];
#pragma unroll 8
    for (int k = 0; k < 32; k++)
        acc += (g_pool[g * 32 + k] / cnt) * Wh1[k * 32 + lane];
    for (int k = 0; k < metaDim; k++)
        acc += meta[(size_t)g * metaDim + k] * Wh1[(32 + k) * 32 + lane];
    acc = fmaxf(acc, 0.f);
    float p = acc * Wh2[lane];
#pragma unroll
    for (int o = 16; o; o >>= 1) p += __shfl_xor_sync(0xffffffffu, p, o);
    if (lane == 0) out[g] = p + bh2[0];
}

// ---------------- host launcher ----------------
extern "C" void kernel_launch(void* const* d_in, const int* in_sizes, int n_in,
                              void* d_out, int out_size)
{
    const float* x     = (const float*)d_in[0];
    const int*   ei    = (const int*)d_in[1];    // int32 (JAX x64 disabled)
    const int*   batch = (const int*)d_in[2];    // int32
    const float* meta  = (const float*)d_in[3];
    const float* Wl[3]  = {(const float*)d_in[4],  (const float*)d_in[10], (const float*)d_in[16]};
    const float* bl[3]  = {(const float*)d_in[5],  (const float*)d_in[11], (const float*)d_in[17]};
    const float* Wr[3]  = {(const float*)d_in[6],  (const float*)d_in[12], (const float*)d_in[18]};
    const float* br[3]  = {(const float*)d_in[7],  (const float*)d_in[13], (const float*)d_in[19]};
    const float* att[3] = {(const float*)d_in[8],  (const float*)d_in[14], (const float*)d_in[20]};
    const float* bc[3]  = {(const float*)d_in[9],  (const float*)d_in[15], (const float*)d_in[21]};
    const float* Wh1 = (const float*)d_in[22];
    const float* bh1 = (const float*)d_in[23];
    const float* Wh2 = (const float*)d_in[24];
    const float* bh2 = (const float*)d_in[25];

    const int N = in_sizes[0] / 128;
    const int E = in_sizes[1] / 2;
    const int metaDim = 12;
    const int B = in_sizes[3] / metaDim;
    const int Etot = E + N;
    const int nb = (N + 1023) / 1024;

    float *xl, *xr, *hA, *hB, *pool, *cnt;
    int *deg;
    cudaGetSymbolAddress((void**)&xl,   g_xl);
    cudaGetSymbolAddress((void**)&xr,   g_xr);
    cudaGetSymbolAddress((void**)&hA,   g_hA);
    cudaGetSymbolAddress((void**)&hB,   g_hB);
    cudaGetSymbolAddress((void**)&pool, g_pool);
    cudaGetSymbolAddress((void**)&cnt,  g_cnt);
    cudaGetSymbolAddress((void**)&deg,  g_deg);

    // ---- build CSR (dst-sorted) ----
    zero_i<<<(N + 255) / 256, 256>>>(deg, N);
    prep_edges<<<(Etot + 255) / 256, 256>>>(ei, E, N);
    scan_local<<<nb, 1024>>>(N);
    scan_tops<<<1, 64>>>(nb);
    scan_add<<<(N + 255) / 256, 256>>>(N);       // also zeroes g_pos
    scatter_edges<<<(Etot + 255) / 256, 256>>>(Etot);

    const int warpGrid = (N * 32 + 255) / 256;

    // ---- layer 0 (H=4) ----
    gemm_f128<<<(N + 127) / 128, 256>>>(x, Wl[0], bl[0], xl, N);
    gemm_f128<<<(N + 127) / 128, 256>>>(x, Wr[0], br[0], xr, N);
    gat_fused<4><<<warpGrid, 256>>>(xl, xr, att[0], bc[0], hA, N);

    // ---- layer 1 (H=4) ----
    gemm_f128<<<(N + 127) / 128, 256>>>(hA, Wl[1], bl[1], xl, N);
    gemm_f128<<<(N + 127) / 128, 256>>>(hA, Wr[1], br[1], xr, N);
    gat_fused<4><<<warpGrid, 256>>>(xl, xr, att[1], bc[1], hB, N);

    // ---- layer 2 (H=1) ----
    {
        dim3 g2(1, (N + 63) / 64);
        gemm128<<<g2, 256>>>(hB, Wl[2], bl[2], xl, N, 32);
        gemm128<<<g2, 256>>>(hB, Wr[2], br[2], xr, N, 32);
    }
    gat_fused<1><<<warpGrid, 256>>>(xl, xr, att[2], bc[2], hA, N);

    // ---- global mean pool + MLP head ----
    zero_f<<<(B * 32 + 255) / 256, 256>>>(pool, B * 32);
    zero_f<<<(B + 255) / 256, 256>>>(cnt, B);
    pool_acc<<<(N * 32 + 255) / 256, 256>>>(hA, batch, N);
    mlp_head<<<(B * 32 + 255) / 256, 256>>>(meta, Wh1, bh1, Wh2, bh2,
                                            (float*)d_out, B, metaDim);
}

// round 6
// speedup vs baseline: 2.4565x; 1.3011x over previous
#include <cuda_runtime.h>
#include <cuda_bf16.h>
#include <math.h>

// ---------------- problem-size constants (fixed dataset) ----------------
#define MAXN 50000
#define MAXE 800000
#define MAXET (MAXN + MAXE)
#define MAXB 512

// ---------------- device scratch (static, no allocation) ----------------
__device__ float g_xl[(size_t)MAXN * 128];
__device__ float g_xr[(size_t)MAXN * 128];
__device__ float g_hA[(size_t)MAXN * 128];
__device__ float g_hB[(size_t)MAXN * 128];
__device__ int   g_src[MAXET];
__device__ int   g_dst[MAXET];
__device__ int   g_deg[MAXN];
__device__ int   g_off[MAXN + 1];
__device__ int   g_pos[MAXN];
__device__ int   g_csr[MAXET];              // src ids sorted by dst
__device__ int   g_bsum[64];                // per-block sums for scan
__device__ float g_pool[MAXB * 32];
__device__ float g_cnt[MAXB];

// ---------------- f32x2 packed-FMA helpers (sm_103a FFMA2 path) ----------------
__device__ __forceinline__ unsigned long long pk2(float x, float y) {
    unsigned long long r;
    asm("mov.b64 %0, {%1, %2};" : "=l"(r) : "f"(x), "f"(y));
    return r;
}
__device__ __forceinline__ void upk2(unsigned long long v, float& x, float& y) {
    asm("mov.b64 {%0, %1}, %2;" : "=f"(x), "=f"(y) : "l"(v));
}
__device__ __forceinline__ unsigned long long ffma2(
    unsigned long long a, unsigned long long b, unsigned long long c) {
    unsigned long long d;
    asm("fma.rn.f32x2 %0, %1, %2, %3;" : "=l"(d) : "l"(a), "l"(b), "l"(c));
    return d;
}

// warp-wide float sum (shfl butterfly; redux.f32 is NOT supported on sm_103)
__device__ __forceinline__ float warp_sum(float v) {
#pragma unroll
    for (int o = 16; o; o >>= 1) v += __shfl_xor_sync(0xffffffffu, v, o);
    return v;
}

// ---------------- small utility kernels ----------------
__global__ void zero_f(float* p, int n) {
    int i = blockIdx.x * blockDim.x + threadIdx.x;
    if (i < n) p[i] = 0.f;
}
__global__ void zero_i(int* p, int n) {
    int i = blockIdx.x * blockDim.x + threadIdx.x;
    if (i < n) p[i] = 0;
}

// edge_index / batch are INT32 (JAX x64 disabled).
__global__ void prep_edges(const int* __restrict__ ei, int E, int N) {
    int i = blockIdx.x * blockDim.x + threadIdx.x;
    int Etot = E + N;
    if (i >= Etot) return;
    int s, d;
    if (i < E) { s = ei[i]; d = ei[E + i]; }
    else       { s = i - E; d = i - E; }
    g_src[i] = s;
    g_dst[i] = d;
    atomicAdd(&g_deg[d], 1);
}

// ---------------- multi-block scan of g_deg -> g_off ----------------
__global__ void scan_local(int N) {
    __shared__ int wsum[32];
    int b = blockIdx.x, tid = threadIdx.x, lane = tid & 31, wid = tid >> 5;
    int i = b * 1024 + tid;
    int x = (i < N) ? g_deg[i] : 0;
#pragma unroll
    for (int o = 1; o < 32; o <<= 1) {
        int y = __shfl_up_sync(0xffffffffu, x, o);
        if (lane >= o) x += y;
    }
    if (lane == 31) wsum[wid] = x;
    __syncthreads();
    if (wid == 0) {
        int s = wsum[lane];
#pragma unroll
        for (int o = 1; o < 32; o <<= 1) {
            int y = __shfl_up_sync(0xffffffffu, s, o);
            if (lane >= o) s += y;
        }
        wsum[lane] = s;
    }
    __syncthreads();
    int incl = x + (wid ? wsum[wid - 1] : 0);
    if (i < N) g_off[i + 1] = incl;
    if (tid == 1023) g_bsum[b] = incl;
}

__global__ void scan_tops(int nb) {
    __shared__ int s[64];
    int tid = threadIdx.x;
    if (tid < nb) s[tid] = g_bsum[tid];
    __syncthreads();
    if (tid == 0) {
        int a = 0;
        for (int i = 0; i < nb; i++) { int t = s[i]; s[i] = a; a += t; }
    }
    __syncthreads();
    if (tid < nb) g_bsum[tid] = s[tid];
}

__global__ void scan_add(int N) {
    int i = blockIdx.x * blockDim.x + threadIdx.x;
    if (i == 0) g_off[0] = 0;
    if (i < N) {
        g_off[i + 1] += g_bsum[i >> 10];
        g_pos[i] = 0;
    }
}

__global__ void scatter_edges(int Etot) {
    int i = blockIdx.x * blockDim.x + threadIdx.x;
    if (i >= Etot) return;
    int d = g_dst[i];
    int p = atomicAdd(&g_pos[d], 1);
    g_csr[g_off[d] + p] = g_src[i];
}

// ---------------- dual GEMM: {xl,xr}[N,128] = A[N,128] @ {Wl,Wr}[128,128] + bias ----------------
// blockIdx.y selects (W0,b0,C0) vs (W1,b1,C1). 128x128 tile, K chunked by 16,
// double-buffered, packed f32x2 FMA.
__global__ __launch_bounds__(256) void gemm_f128_dual(
    const float* __restrict__ A,
    const float* __restrict__ W0, const float* __restrict__ b0, float* __restrict__ C0,
    const float* __restrict__ W1, const float* __restrict__ b1, float* __restrict__ C1,
    int N)
{
    const float* W    = blockIdx.y ? W1 : W0;
    const float* bias = blockIdx.y ? b1 : b0;
    float*       C    = blockIdx.y ? C1 : C0;

    __shared__ float Ast[2][16][130];   // [buf][k][row] transposed, padded
    __shared__ float Wst[2][16][128];   // [buf][k][col]
    const int t = threadIdx.x;
    const int row0 = blockIdx.x * 128;
    const int tx = t & 15, ty = t >> 4;   // 16x16 thread grid
    const int r0 = ty * 8, c0 = tx * 8;

    unsigned long long acc[4][8];
#pragma unroll
    for (int p = 0; p < 4; p++)
#pragma unroll
        for (int j = 0; j < 8; j++) acc[p][j] = pk2(0.f, 0.f);

    const int ar[2]  = {(t + 0) >> 2,   (t + 256) >> 2};
    const int ac4[2] = {(t + 0) & 3,    (t + 256) & 3};
    const int wk[2]  = {(t + 0) >> 5,   (t + 256) >> 5};
    const int wc4[2] = {(t + 0) & 31,   (t + 256) & 31};

    float4 aR[2], wR[2];

#pragma unroll
    for (int i = 0; i < 2; i++) {
        int gr = row0 + ar[i];
        aR[i] = (gr < N) ? *(const float4*)&A[(size_t)gr * 128 + ac4[i] * 4]
                         : make_float4(0.f, 0.f, 0.f, 0.f);
        wR[i] = *(const float4*)&W[(size_t)wk[i] * 128 + wc4[i] * 4];
    }
#pragma unroll
    for (int i = 0; i < 2; i++) {
        Ast[0][ac4[i] * 4 + 0][ar[i]] = aR[i].x;
        Ast[0][ac4[i] * 4 + 1][ar[i]] = aR[i].y;
        Ast[0][ac4[i] * 4 + 2][ar[i]] = aR[i].z;
        Ast[0][ac4[i] * 4 + 3][ar[i]] = aR[i].w;
        *(float4*)&Wst[0][wk[i]][wc4[i] * 4] = wR[i];
    }
    __syncthreads();

    for (int kc = 0; kc < 8; kc++) {
        int b = kc & 1;
        if (kc < 7) {
#pragma unroll
            for (int i = 0; i < 2; i++) {
                int gr = row0 + ar[i];
                aR[i] = (gr < N) ? *(const float4*)&A[(size_t)gr * 128 + (kc + 1) * 16 + ac4[i] * 4]
                                 : make_float4(0.f, 0.f, 0.f, 0.f);
                wR[i] = *(const float4*)&W[(size_t)((kc + 1) * 16 + wk[i]) * 128 + wc4[i] * 4];
            }
        }
#pragma unroll
        for (int k = 0; k < 16; k++) {
            unsigned long long av[4];
#pragma unroll
            for (int p = 0; p < 4; p++) {
                float2 a2 = *(const float2*)&Ast[b][k][r0 + p * 2];
                av[p] = pk2(a2.x, a2.y);
            }
            float4 w0 = *(const float4*)&Wst[b][k][c0];
            float4 w1 = *(const float4*)&Wst[b][k][c0 + 4];
            unsigned long long wd[8];
            wd[0] = pk2(w0.x, w0.x); wd[1] = pk2(w0.y, w0.y);
            wd[2] = pk2(w0.z, w0.z); wd[3] = pk2(w0.w, w0.w);
            wd[4] = pk2(w1.x, w1.x); wd[5] = pk2(w1.y, w1.y);
            wd[6] = pk2(w1.z, w1.z); wd[7] = pk2(w1.w, w1.w);
#pragma unroll
            for (int p = 0; p < 4; p++)
#pragma unroll
                for (int j = 0; j < 8; j++)
                    acc[p][j] = ffma2(av[p], wd[j], acc[p][j]);
        }
        if (kc < 7) {
            int nb = b ^ 1;
#pragma unroll
            for (int i = 0; i < 2; i++) {
                Ast[nb][ac4[i] * 4 + 0][ar[i]] = aR[i].x;
                Ast[nb][ac4[i] * 4 + 1][ar[i]] = aR[i].y;
                Ast[nb][ac4[i] * 4 + 2][ar[i]] = aR[i].z;
                Ast[nb][ac4[i] * 4 + 3][ar[i]] = aR[i].w;
                *(float4*)&Wst[nb][wk[i]][wc4[i] * 4] = wR[i];
            }
            __syncthreads();
        }
    }

#pragma unroll
    for (int p = 0; p < 4; p++) {
        int rA = row0 + r0 + p * 2;
        int rB = rA + 1;
#pragma unroll
        for (int j = 0; j < 8; j++) {
            float lo, hi;
            upk2(acc[p][j], lo, hi);
            int c = c0 + j;
            if (rA < N) C[(size_t)rA * 128 + c] = lo + bias[c];
            if (rB < N) C[(size_t)rB * 128 + c] = hi + bias[c];
        }
    }
}

// ---------------- dual small GEMM (M=32): {xl,xr}[N,32] = A[N,128] @ W[128,32] + bias ----------------
__global__ __launch_bounds__(256) void gemm128_dual(
    const float* __restrict__ A,
    const float* __restrict__ W0, const float* __restrict__ b0, float* __restrict__ C0,
    const float* __restrict__ W1, const float* __restrict__ b1, float* __restrict__ C1,
    int N)
{
    const int M = 32;
    const float* W    = blockIdx.y ? W1 : W0;
    const float* bias = blockIdx.y ? b1 : b0;
    float*       C    = blockIdx.y ? C1 : C0;

    __shared__ float As[16][64];
    __shared__ float Ws[16][64];
    const int t = threadIdx.x;
    const int row0 = blockIdx.x * 64;
    const int tx = t & 15, ty = t >> 4;

    float acc[4][4];
#pragma unroll
    for (int i = 0; i < 4; i++)
#pragma unroll
        for (int j = 0; j < 4; j++) acc[i][j] = 0.f;

    for (int k0 = 0; k0 < 128; k0 += 16) {
#pragma unroll
        for (int i = 0; i < 4; i++) {
            int idx = t + i * 256;
            int r = idx >> 4, c = idx & 15;
            int gr = row0 + r;
            As[c][r] = (gr < N) ? A[(size_t)gr * 128 + k0 + c] : 0.f;
        }
#pragma unroll
        for (int i = 0; i < 4; i++) {
            int idx = t + i * 256;
            int kk = idx >> 6, cc = idx & 63;
            Ws[kk][cc] = (cc < M) ? W[(size_t)(k0 + kk) * M + cc] : 0.f;
        }
        __syncthreads();
#pragma unroll
        for (int kk = 0; kk < 16; kk++) {
            float4 a4 = *(const float4*)&As[kk][ty * 4];
            float4 w4 = *(const float4*)&Ws[kk][tx * 4];
            float a[4] = {a4.x, a4.y, a4.z, a4.w};
            float w[4] = {w4.x, w4.y, w4.z, w4.w};
#pragma unroll
            for (int i = 0; i < 4; i++)
#pragma unroll
                for (int j = 0; j < 4; j++) acc[i][j] += a[i] * w[j];
        }
        __syncthreads();
    }
#pragma unroll
    for (int i = 0; i < 4; i++) {
        int r = row0 + ty * 4 + i;
        if (r >= N) continue;
#pragma unroll
        for (int j = 0; j < 4; j++) {
            int c = tx * 4 + j;
            if (c < M) C[(size_t)r * M + c] = acc[i][j] + bias[c];
        }
    }
}

// ---------------- transposed fused GATv2 (H=4): one warp per dst node ----------------
// Lane l owns float4 [l*4 .. l*4+3] of the 128-wide feature row; each 8-lane
// group owns one head. Per edge: one LDG.128/lane, 4-FMA local dot,
// 3-shfl group reduce, branchless online softmax.
__global__ void gat4_t(const float* __restrict__ xl, const float* __restrict__ xr,
                       const float* __restrict__ att, const float* __restrict__ bias,
                       float* __restrict__ out, int N)
{
    int w = (blockIdx.x * blockDim.x + threadIdx.x) >> 5;
    if (w >= N) return;
    int lane = threadIdx.x & 31;

    const float4 xrv  = *(const float4*)&xr[(size_t)w * 128 + lane * 4];
    const float4 attv = *(const float4*)&att[lane * 4];
    float mx = -1e30f, den = 0.f;
    float4 acc = make_float4(0.f, 0.f, 0.f, 0.f);

    const int j0 = g_off[w], j1 = g_off[w + 1];
    int s = g_csr[j0];
    float4 v = *(const float4*)&xl[(size_t)s * 128 + lane * 4];

    for (int j = j0; j < j1; j++) {
        int jn = (j + 1 < j1) ? j + 1 : j;
        int sn = g_csr[jn];
        float4 vn = *(const float4*)&xl[(size_t)sn * 128 + lane * 4];

        // leaky_relu(v + xr, 0.2) = max(t, 0.2t)
        float t0 = v.x + xrv.x; t0 = fmaxf(t0, 0.2f * t0);
        float t1 = v.y + xrv.y; t1 = fmaxf(t1, 0.2f * t1);
        float t2 = v.z + xrv.z; t2 = fmaxf(t2, 0.2f * t2);
        float t3 = v.w + xrv.w; t3 = fmaxf(t3, 0.2f * t3);
        float p = t0 * attv.x + t1 * attv.y + t2 * attv.z + t3 * attv.w;
        p += __shfl_xor_sync(0xffffffffu, p, 1);
        p += __shfl_xor_sync(0xffffffffu, p, 2);
        p += __shfl_xor_sync(0xffffffffu, p, 4);   // head logit, replicated in 8-lane group

        float nm = fmaxf(mx, p);
        float sc = __expf(mx - nm);                // first iter: exp(-huge)=0
        float e  = __expf(p - nm);
        mx = nm;
        den = den * sc + e;
        acc.x = acc.x * sc + e * v.x;
        acc.y = acc.y * sc + e * v.y;
        acc.z = acc.z * sc + e * v.z;
        acc.w = acc.w * sc + e * v.w;
        v = vn;
    }

    float inv = 1.f / (den + 1e-16f);
    float4 bv = *(const float4*)&bias[lane * 4];
    float4 o;
    o.x = acc.x * inv + bv.x; o.x = o.x > 0.f ? o.x : expm1f(o.x);
    o.y = acc.y * inv + bv.y; o.y = o.y > 0.f ? o.y : expm1f(o.y);
    o.z = acc.z * inv + bv.z; o.z = o.z > 0.f ? o.z : expm1f(o.z);
    o.w = acc.w * inv + bv.w; o.w = o.w > 0.f ? o.w : expm1f(o.w);
    *(float4*)&out[(size_t)w * 128 + lane * 4] = o;
}

// ---------------- fused GATv2 (H=1): one warp per dst node, lane=channel ----------------
__global__ void gat1(const float* __restrict__ xl, const float* __restrict__ xr,
                     const float* __restrict__ att, const float* __restrict__ bias,
                     float* __restrict__ out, int N)
{
    int w = (blockIdx.x * blockDim.x + threadIdx.x) >> 5;
    if (w >= N) return;
    int lane = threadIdx.x & 31;

    float xrv  = xr[(size_t)w * 32 + lane];
    float attv = att[lane];
    float mx = -1e30f, den = 0.f, acc = 0.f;

    const int j0 = g_off[w], j1 = g_off[w + 1];
    int s = g_csr[j0];
    float v = xl[(size_t)s * 32 + lane];

    for (int j = j0; j < j1; j++) {
        int jn = (j + 1 < j1) ? j + 1 : j;
        int sn = g_csr[jn];
        float vn = xl[(size_t)sn * 32 + lane];

        float t = v + xrv;
        t = fmaxf(t, 0.2f * t);
        float p = warp_sum(t * attv);

        float nm = fmaxf(mx, p);
        float sc = __expf(mx - nm);
        float e  = __expf(p - nm);
        mx = nm;
        den = den * sc + e;
        acc = acc * sc + e * v;
        v = vn;
    }

    float o = acc / (den + 1e-16f) + bias[lane];
    o = o > 0.f ? o : expm1f(o);
    out[(size_t)w * 32 + lane] = o;
}

// ---------------- graph mean pool (accumulate) ----------------
__global__ void pool_acc(const float* __restrict__ h, const int* __restrict__ batch, int N)
{
    int n = (blockIdx.x * blockDim.x + threadIdx.x) >> 5;
    int lane = threadIdx.x & 31;
    if (n >= N) return;
    int b = batch[n];
    atomicAdd(&g_pool[b * 32 + lane], h[(size_t)n * 32 + lane]);
    if (lane == 0) atomicAdd(&g_cnt[b], 1.f);
}

// ---------------- final MLP head: one warp per graph ----------------
__global__ void mlp_head(const float* __restrict__ meta,
                         const float* __restrict__ Wh1, const float* __restrict__ bh1,
                         const float* __restrict__ Wh2, const float* __restrict__ bh2,
                         float* __restrict__ out, int B, int metaDim)
{
    int g = (blockIdx.x * blockDim.x + threadIdx.x) >> 5;
    int lane = threadIdx.x & 31;
    if (g >= B) return;
    float cnt = fmaxf(g_cnt[g], 1.f);
    float acc = bh1[lane];
#pragma unroll 8
    for (int k = 0; k < 32; k++)
        acc += (g_pool[g * 32 + k] / cnt) * Wh1[k * 32 + lane];
    for (int k = 0; k < metaDim; k++)
        acc += meta[(size_t)g * metaDim + k] * Wh1[(32 + k) * 32 + lane];
    acc = fmaxf(acc, 0.f);
    float p = acc * Wh2[lane];
#pragma unroll
    for (int o = 16; o; o >>= 1) p += __shfl_xor_sync(0xffffffffu, p, o);
    if (lane == 0) out[g] = p + bh2[0];
}

// ---------------- host launcher ----------------
extern "C" void kernel_launch(void* const* d_in, const int* in_sizes, int n_in,
                              void* d_out, int out_size)
{
    const float* x     = (const float*)d_in[0];
    const int*   ei    = (const int*)d_in[1];    // int32 (JAX x64 disabled)
    const int*   batch = (const int*)d_in[2];    // int32
    const float* meta  = (const float*)d_in[3];
    const float* Wl[3]  = {(const float*)d_in[4],  (const float*)d_in[10], (const float*)d_in[16]};
    const float* bl[3]  = {(const float*)d_in[5],  (const float*)d_in[11], (const float*)d_in[17]};
    const float* Wr[3]  = {(const float*)d_in[6],  (const float*)d_in[12], (const float*)d_in[18]};
    const float* br[3]  = {(const float*)d_in[7],  (const float*)d_in[13], (const float*)d_in[19]};
    const float* att[3] = {(const float*)d_in[8],  (const float*)d_in[14], (const float*)d_in[20]};
    const float* bc[3]  = {(const float*)d_in[9],  (const float*)d_in[15], (const float*)d_in[21]};
    const float* Wh1 = (const float*)d_in[22];
    const float* bh1 = (const float*)d_in[23];
    const float* Wh2 = (const float*)d_in[24];
    const float* bh2 = (const float*)d_in[25];

    const int N = in_sizes[0] / 128;
    const int E = in_sizes[1] / 2;
    const int metaDim = 12;
    const int B = in_sizes[3] / metaDim;
    const int Etot = E + N;
    const int nb = (N + 1023) / 1024;

    float *xl, *xr, *hA, *hB, *pool, *cnt;
    int *deg;
    cudaGetSymbolAddress((void**)&xl,   g_xl);
    cudaGetSymbolAddress((void**)&xr,   g_xr);
    cudaGetSymbolAddress((void**)&hA,   g_hA);
    cudaGetSymbolAddress((void**)&hB,   g_hB);
    cudaGetSymbolAddress((void**)&pool, g_pool);
    cudaGetSymbolAddress((void**)&cnt,  g_cnt);
    cudaGetSymbolAddress((void**)&deg,  g_deg);

    const int warpGrid = (N * 32 + 255) / 256;
    const dim3 bigGrid((N + 127) / 128, 2);
    const dim3 smallGrid((N + 63) / 64, 2);

    // ---- CSR build interleaved with layer-0 GEMM (GEMM early for ncu slot) ----
    zero_i<<<(N + 255) / 256, 256>>>(deg, N);                              // 0
    prep_edges<<<(Etot + 255) / 256, 256>>>(ei, E, N);                     // 1
    scan_local<<<nb, 1024>>>(N);                                           // 2
    gemm_f128_dual<<<bigGrid, 256>>>(x, Wl[0], bl[0], xl,
                                        Wr[0], br[0], xr, N);              // 3 (ncu)
    scan_tops<<<1, 64>>>(nb);                                              // 4
    scan_add<<<(N + 255) / 256, 256>>>(N);       // also zeroes g_pos      // 5
    scatter_edges<<<(Etot + 255) / 256, 256>>>(Etot);                      // 6

    // ---- layer 0 (H=4) ----
    gat4_t<<<warpGrid, 256>>>(xl, xr, att[0], bc[0], hA, N);

    // ---- layer 1 (H=4) ----
    gemm_f128_dual<<<bigGrid, 256>>>(hA, Wl[1], bl[1], xl,
                                         Wr[1], br[1], xr, N);
    gat4_t<<<warpGrid, 256>>>(xl, xr, att[1], bc[1], hB, N);

    // ---- layer 2 (H=1) ----
    gemm128_dual<<<smallGrid, 256>>>(hB, Wl[2], bl[2], xl,
                                         Wr[2], br[2], xr, N);
    gat1<<<warpGrid, 256>>>(xl, xr, att[2], bc[2], hA, N);

    // ---- global mean pool + MLP head ----
    zero_f<<<(B * 32 + 255) / 256, 256>>>(pool, B * 32);
    zero_f<<<(B + 255) / 256, 256>>>(cnt, B);
    pool_acc<<<(N * 32 + 255) / 256, 256>>>(hA, batch, N);
    mlp_head<<<(B * 32 + 255) / 256, 256>>>(meta, Wh1, bh1, Wh2, bh2,
                                            (float*)d_out, B, metaDim);
}

// round 8
// speedup vs baseline: 3.5707x; 1.4536x over previous
#include <cuda_runtime.h>
#include <cuda_bf16.h>
#include <math.h>

// ---------------- problem-size constants (fixed dataset) ----------------
#define MAXN 50000
#define MAXE 800000
#define MAXET (MAXN + MAXE)
#define MAXB 512

// ---------------- device scratch (static, no allocation) ----------------
__device__ float g_xl[(size_t)MAXN * 128];
__device__ float g_xr[(size_t)MAXN * 128];
__device__ float g_hA[(size_t)MAXN * 128];
__device__ float g_hB[(size_t)MAXN * 128];
__device__ int   g_src[MAXET];
__device__ int   g_dst[MAXET];
__device__ int   g_deg[MAXN];
__device__ int   g_off[MAXN + 1];
__device__ int   g_pos[MAXN];
__device__ int   g_csr[MAXET];              // src ids sorted by dst
__device__ int   g_bsum[64];                // per-block sums for scan
__device__ float g_pool[MAXB * 32];
__device__ float g_cnt[MAXB];

// ---------------- helpers ----------------
__device__ __forceinline__ float warp_sum(float v) {
#pragma unroll
    for (int o = 16; o; o >>= 1) v += __shfl_xor_sync(0xffffffffu, v, o);
    return v;
}

__device__ __forceinline__ unsigned f2tf32(float f) {
    unsigned u;
    asm("cvt.rna.tf32.f32 %0, %1;" : "=r"(u) : "f"(f));
    return u;
}

__device__ __forceinline__ void mma_tf32(float* d, const unsigned* a, const unsigned* b) {
    asm volatile(
        "mma.sync.aligned.m16n8k8.row.col.f32.tf32.tf32.f32 "
        "{%0,%1,%2,%3}, {%4,%5,%6,%7}, {%8,%9}, {%0,%1,%2,%3};"
        : "+f"(d[0]), "+f"(d[1]), "+f"(d[2]), "+f"(d[3])
        : "r"(a[0]), "r"(a[1]), "r"(a[2]), "r"(a[3]), "r"(b[0]), "r"(b[1]));
}

// ---------------- small utility kernels ----------------
__global__ void zero_f(float* p, int n) {
    int i = blockIdx.x * blockDim.x + threadIdx.x;
    if (i < n) p[i] = 0.f;
}
__global__ void zero_i(int* p, int n) {
    int i = blockIdx.x * blockDim.x + threadIdx.x;
    if (i < n) p[i] = 0;
}

// edge_index / batch are INT32 (JAX x64 disabled).
__global__ void prep_edges(const int* __restrict__ ei, int E, int N) {
    int i = blockIdx.x * blockDim.x + threadIdx.x;
    int Etot = E + N;
    if (i >= Etot) return;
    int s, d;
    if (i < E) { s = ei[i]; d = ei[E + i]; }
    else       { s = i - E; d = i - E; }
    g_src[i] = s;
    g_dst[i] = d;
    atomicAdd(&g_deg[d], 1);
}

// ---------------- multi-block scan of g_deg -> g_off ----------------
__global__ void scan_local(int N) {
    __shared__ int wsum[32];
    int b = blockIdx.x, tid = threadIdx.x, lane = tid & 31, wid = tid >> 5;
    int i = b * 1024 + tid;
    int x = (i < N) ? g_deg[i] : 0;
#pragma unroll
    for (int o = 1; o < 32; o <<= 1) {
        int y = __shfl_up_sync(0xffffffffu, x, o);
        if (lane >= o) x += y;
    }
    if (lane == 31) wsum[wid] = x;
    __syncthreads();
    if (wid == 0) {
        int s = wsum[lane];
#pragma unroll
        for (int o = 1; o < 32; o <<= 1) {
            int y = __shfl_up_sync(0xffffffffu, s, o);
            if (lane >= o) s += y;
        }
        wsum[lane] = s;
    }
    __syncthreads();
    int incl = x + (wid ? wsum[wid - 1] : 0);
    if (i < N) g_off[i + 1] = incl;
    if (tid == 1023) g_bsum[b] = incl;
}

__global__ void scan_tops(int nb) {
    __shared__ int s[64];
    int tid = threadIdx.x;
    if (tid < nb) s[tid] = g_bsum[tid];
    __syncthreads();
    if (tid == 0) {
        int a = 0;
        for (int i = 0; i < nb; i++) { int t = s[i]; s[i] = a; a += t; }
    }
    __syncthreads();
    if (tid < nb) g_bsum[tid] = s[tid];
}

__global__ void scan_add(int N) {
    int i = blockIdx.x * blockDim.x + threadIdx.x;
    if (i == 0) g_off[0] = 0;
    if (i < N) {
        g_off[i + 1] += g_bsum[i >> 10];
        g_pos[i] = 0;
    }
}

__global__ void scatter_edges(int Etot) {
    int i = blockIdx.x * blockDim.x + threadIdx.x;
    if (i >= Etot) return;
    int d = g_dst[i];
    int p = atomicAdd(&g_pos[d], 1);
    g_csr[g_off[d] + p] = g_src[i];
}

// ---------------- tf32 tensor-core dual GEMM ----------------
// {xl,xr}[N,128] = A[N,128] @ {Wl,Wr}[128,128] + bias,  blockIdx.y selects set.
// 128x128 block tile, 8 warps (4m x 2n), warp tile 32x64 via m16n8k8 tf32 mma.
__global__ __launch_bounds__(256, 2) void gemm_tc_dual(
    const float* __restrict__ A,
    const float* __restrict__ W0, const float* __restrict__ b0, float* __restrict__ C0,
    const float* __restrict__ W1, const float* __restrict__ b1, float* __restrict__ C1,
    int N)
{
    const float* W    = blockIdx.y ? W1 : W0;
    const float* bias = blockIdx.y ? b1 : b0;
    float*       C    = blockIdx.y ? C1 : C0;

    __shared__ unsigned A_s[128][36];   // [row][k within 32-chunk], pad 4
    __shared__ unsigned W_s[32][136];   // [k within chunk][col], pad 8

    const int t    = threadIdx.x;
    const int wid  = t >> 5;
    const int lane = t & 31;
    const int gid  = lane >> 2;         // groupID 0..7
    const int tig  = lane & 3;          // thread-in-group 0..3
    const int wm   = wid & 3;           // 4 warps along M (32 rows each)
    const int wn   = wid >> 2;          // 2 warps along N (64 cols each)
    const int row0 = blockIdx.x * 128;

    float acc[2][8][4];
#pragma unroll
    for (int km = 0; km < 2; km++)
#pragma unroll
        for (int n = 0; n < 8; n++)
#pragma unroll
            for (int c = 0; c < 4; c++) acc[km][n][c] = 0.f;

    for (int kc = 0; kc < 4; kc++) {
        // ---- stage A[128][32] and W[32][128] chunk to smem as tf32 ----
#pragma unroll
        for (int i = 0; i < 4; i++) {
            int q = t + i * 256;                 // 0..1023
            // A: 128 rows x 8 float4
            int r = q >> 3, c4 = q & 7;
            float4 a4 = make_float4(0.f, 0.f, 0.f, 0.f);
            if (row0 + r < N)
                a4 = *(const float4*)&A[(size_t)(row0 + r) * 128 + kc * 32 + c4 * 4];
            uint4 ua;
            ua.x = f2tf32(a4.x); ua.y = f2tf32(a4.y);
            ua.z = f2tf32(a4.z); ua.w = f2tf32(a4.w);
            *(uint4*)&A_s[r][c4 * 4] = ua;
            // W: 32 rows x 32 float4
            int k = q >> 5, c32 = q & 31;
            float4 w4 = *(const float4*)&W[(size_t)(kc * 32 + k) * 128 + c32 * 4];
            uint4 uw;
            uw.x = f2tf32(w4.x); uw.y = f2tf32(w4.y);
            uw.z = f2tf32(w4.z); uw.w = f2tf32(w4.w);
            *(uint4*)&W_s[k][c32 * 4] = uw;
        }
        __syncthreads();

        // ---- 4 k-steps of 8 within this chunk ----
#pragma unroll
        for (int ks = 0; ks < 4; ks++) {
            const int kq = ks * 8;
            unsigned a[2][4], b[8][2];
#pragma unroll
            for (int km = 0; km < 2; km++) {
                int rb = wm * 32 + km * 16 + gid;
                a[km][0] = A_s[rb    ][kq + tig];
                a[km][1] = A_s[rb + 8][kq + tig];
                a[km][2] = A_s[rb    ][kq + tig + 4];
                a[km][3] = A_s[rb + 8][kq + tig + 4];
            }
#pragma unroll
            for (int n = 0; n < 8; n++) {
                int cb = wn * 64 + n * 8 + gid;
                b[n][0] = W_s[kq + tig    ][cb];
                b[n][1] = W_s[kq + tig + 4][cb];
            }
#pragma unroll
            for (int km = 0; km < 2; km++)
#pragma unroll
                for (int n = 0; n < 8; n++)
                    mma_tf32(acc[km][n], a[km], b[n]);
        }
        __syncthreads();
    }

    // ---- epilogue: add bias, store ----
#pragma unroll
    for (int km = 0; km < 2; km++) {
        int rA = row0 + wm * 32 + km * 16 + gid;
        int rB = rA + 8;
#pragma unroll
        for (int n = 0; n < 8; n++) {
            int col = wn * 64 + n * 8 + 2 * tig;
            float bx = bias[col], by = bias[col + 1];
            if (rA < N) {
                float2 o = make_float2(acc[km][n][0] + bx, acc[km][n][1] + by);
                *(float2*)&C[(size_t)rA * 128 + col] = o;
            }
            if (rB < N) {
                float2 o = make_float2(acc[km][n][2] + bx, acc[km][n][3] + by);
                *(float2*)&C[(size_t)rB * 128 + col] = o;
            }
        }
    }
}

// ---------------- dual small GEMM (M=32): {xl,xr}[N,32] = A[N,128] @ W[128,32] + bias ----------------
__global__ __launch_bounds__(256) void gemm128_dual(
    const float* __restrict__ A,
    const float* __restrict__ W0, const float* __restrict__ b0, float* __restrict__ C0,
    const float* __restrict__ W1, const float* __restrict__ b1, float* __restrict__ C1,
    int N)
{
    const int M = 32;
    const float* W    = blockIdx.y ? W1 : W0;
    const float* bias = blockIdx.y ? b1 : b0;
    float*       C    = blockIdx.y ? C1 : C0;

    __shared__ float As[16][64];
    __shared__ float Ws[16][64];
    const int t = threadIdx.x;
    const int row0 = blockIdx.x * 64;
    const int tx = t & 15, ty = t >> 4;

    float acc[4][4];
#pragma unroll
    for (int i = 0; i < 4; i++)
#pragma unroll
        for (int j = 0; j < 4; j++) acc[i][j] = 0.f;

    for (int k0 = 0; k0 < 128; k0 += 16) {
#pragma unroll
        for (int i = 0; i < 4; i++) {
            int idx = t + i * 256;
            int r = idx >> 4, c = idx & 15;
            int gr = row0 + r;
            As[c][r] = (gr < N) ? A[(size_t)gr * 128 + k0 + c] : 0.f;
        }
#pragma unroll
        for (int i = 0; i < 4; i++) {
            int idx = t + i * 256;
            int kk = idx >> 6, cc = idx & 63;
            Ws[kk][cc] = (cc < M) ? W[(size_t)(k0 + kk) * M + cc] : 0.f;
        }
        __syncthreads();
#pragma unroll
        for (int kk = 0; kk < 16; kk++) {
            float4 a4 = *(const float4*)&As[kk][ty * 4];
            float4 w4 = *(const float4*)&Ws[kk][tx * 4];
            float a[4] = {a4.x, a4.y, a4.z, a4.w};
            float w[4] = {w4.x, w4.y, w4.z, w4.w};
#pragma unroll
            for (int i = 0; i < 4; i++)
#pragma unroll
                for (int j = 0; j < 4; j++) acc[i][j] += a[i] * w[j];
        }
        __syncthreads();
    }
#pragma unroll
    for (int i = 0; i < 4; i++) {
        int r = row0 + ty * 4 + i;
        if (r >= N) continue;
#pragma unroll
        for (int j = 0; j < 4; j++) {
            int c = tx * 4 + j;
            if (c < M) C[(size_t)r * M + c] = acc[i][j] + bias[c];
        }
    }
}

// ---------------- transposed fused GATv2 (H=4): one warp per dst node ----------------
__global__ void gat4_t(const float* __restrict__ xl, const float* __restrict__ xr,
                       const float* __restrict__ att, const float* __restrict__ bias,
                       float* __restrict__ out, int N)
{
    int w = (blockIdx.x * blockDim.x + threadIdx.x) >> 5;
    if (w >= N) return;
    int lane = threadIdx.x & 31;

    const float4 xrv  = *(const float4*)&xr[(size_t)w * 128 + lane * 4];
    const float4 attv = *(const float4*)&att[lane * 4];
    float mx = -1e30f, den = 0.f;
    float4 acc = make_float4(0.f, 0.f, 0.f, 0.f);

    const int j0 = g_off[w], j1 = g_off[w + 1];
    int s = g_csr[j0];
    float4 v = *(const float4*)&xl[(size_t)s * 128 + lane * 4];

    for (int j = j0; j < j1; j++) {
        int jn = (j + 1 < j1) ? j + 1 : j;
        int sn = g_csr[jn];
        float4 vn = *(const float4*)&xl[(size_t)sn * 128 + lane * 4];

        float t0 = v.x + xrv.x; t0 = fmaxf(t0, 0.2f * t0);
        float t1 = v.y + xrv.y; t1 = fmaxf(t1, 0.2f * t1);
        float t2 = v.z + xrv.z; t2 = fmaxf(t2, 0.2f * t2);
        float t3 = v.w + xrv.w; t3 = fmaxf(t3, 0.2f * t3);
        float p = t0 * attv.x + t1 * attv.y + t2 * attv.z + t3 * attv.w;
        p += __shfl_xor_sync(0xffffffffu, p, 1);
        p += __shfl_xor_sync(0xffffffffu, p, 2);
        p += __shfl_xor_sync(0xffffffffu, p, 4);   // head logit in 8-lane group

        float nm = fmaxf(mx, p);
        float sc = __expf(mx - nm);                // first iter: exp(-huge)=0
        float e  = __expf(p - nm);
        mx = nm;
        den = den * sc + e;
        acc.x = acc.x * sc + e * v.x;
        acc.y = acc.y * sc + e * v.y;
        acc.z = acc.z * sc + e * v.z;
        acc.w = acc.w * sc + e * v.w;
        v = vn;
    }

    float inv = 1.f / (den + 1e-16f);
    float4 bv = *(const float4*)&bias[lane * 4];
    float4 o;
    o.x = acc.x * inv + bv.x; o.x = o.x > 0.f ? o.x : expm1f(o.x);
    o.y = acc.y * inv + bv.y; o.y = o.y > 0.f ? o.y : expm1f(o.y);
    o.z = acc.z * inv + bv.z; o.z = o.z > 0.f ? o.z : expm1f(o.z);
    o.w = acc.w * inv + bv.w; o.w = o.w > 0.f ? o.w : expm1f(o.w);
    *(float4*)&out[(size_t)w * 128 + lane * 4] = o;
}

// ---------------- fused GATv2 (H=1): one warp per dst node, lane=channel ----------------
__global__ void gat1(const float* __restrict__ xl, const float* __restrict__ xr,
                     const float* __restrict__ att, const float* __restrict__ bias,
                     float* __restrict__ out, int N)
{
    int w = (blockIdx.x * blockDim.x + threadIdx.x) >> 5;
    if (w >= N) return;
    int lane = threadIdx.x & 31;

    float xrv  = xr[(size_t)w * 32 + lane];
    float attv = att[lane];
    float mx = -1e30f, den = 0.f, acc = 0.f;

    const int j0 = g_off[w], j1 = g_off[w + 1];
    int s = g_csr[j0];
    float v = xl[(size_t)s * 32 + lane];

    for (int j = j0; j < j1; j++) {
        int jn = (j + 1 < j1) ? j + 1 : j;
        int sn = g_csr[jn];
        float vn = xl[(size_t)sn * 32 + lane];

        float t = v + xrv;
        t = fmaxf(t, 0.2f * t);
        float p = warp_sum(t * attv);

        float nm = fmaxf(mx, p);
        float sc = __expf(mx - nm);
        float e  = __expf(p - nm);
        mx = nm;
        den = den * sc + e;
        acc = acc * sc + e * v;
        v = vn;
    }

    float o = acc / (den + 1e-16f) + bias[lane];
    o = o > 0.f ? o : expm1f(o);
    out[(size_t)w * 32 + lane] = o;
}

// ---------------- graph mean pool (accumulate) ----------------
__global__ void pool_acc(const float* __restrict__ h, const int* __restrict__ batch, int N)
{
    int n = (blockIdx.x * blockDim.x + threadIdx.x) >> 5;
    int lane = threadIdx.x & 31;
    if (n >= N) return;
    int b = batch[n];
    atomicAdd(&g_pool[b * 32 + lane], h[(size_t)n * 32 + lane]);
    if (lane == 0) atomicAdd(&g_cnt[b], 1.f);
}

// ---------------- final MLP head: one warp per graph ----------------
__global__ void mlp_head(const float* __restrict__ meta,
                         const float* __restrict__ Wh1, const float* __restrict__ bh1,
                         const float* __restrict__ Wh2, const float* __restrict__ bh2,
                         float* __restrict__ out, int B, int metaDim)
{
    int g = (blockIdx.x * blockDim.x + threadIdx.x) >> 5;
    int lane = threadIdx.x & 31;
    if (g >= B) return;
    float cnt = fmaxf(g_cnt[g], 1.f);
    float acc = bh1[lane];
#pragma unroll 8
    for (int k = 0; k < 32; k++)
        acc += (g_pool[g * 32 + k] / cnt) * Wh1[k * 32 + lane];
    for (int k = 0; k < metaDim; k++)
        acc += meta[(size_t)g * metaDim + k] * Wh1[(32 + k) * 32 + lane];
    acc = fmaxf(acc, 0.f);
    float p = acc * Wh2[lane];
#pragma unroll
    for (int o = 16; o; o >>= 1) p += __shfl_xor_sync(0xffffffffu, p, o);
    if (lane == 0) out[g] = p + bh2[0];
}

// ---------------- host launcher ----------------
extern "C" void kernel_launch(void* const* d_in, const int* in_sizes, int n_in,
                              void* d_out, int out_size)
{
    const float* x     = (const float*)d_in[0];
    const int*   ei    = (const int*)d_in[1];    // int32 (JAX x64 disabled)
    const int*   batch = (const int*)d_in[2];    // int32
    const float* meta  = (const float*)d_in[3];
    const float* Wl[3]  = {(const float*)d_in[4],  (const float*)d_in[10], (const float*)d_in[16]};
    const float* bl[3]  = {(const float*)d_in[5],  (const float*)d_in[11], (const float*)d_in[17]};
    const float* Wr[3]  = {(const float*)d_in[6],  (const float*)d_in[12], (const float*)d_in[18]};
    const float* br[3]  = {(const float*)d_in[7],  (const float*)d_in[13], (const float*)d_in[19]};
    const float* att[3] = {(const float*)d_in[8],  (const float*)d_in[14], (const float*)d_in[20]};
    const float* bc[3]  = {(const float*)d_in[9],  (const float*)d_in[15], (const float*)d_in[21]};
    const float* Wh1 = (const float*)d_in[22];
    const float* bh1 = (const float*)d_in[23];
    const float* Wh2 = (const float*)d_in[24];
    const float* bh2 = (const float*)d_in[25];

    const int N = in_sizes[0] / 128;
    const int E = in_sizes[1] / 2;
    const int metaDim = 12;
    const int B = in_sizes[3] / metaDim;
    const int Etot = E + N;
    const int nb = (N + 1023) / 1024;

    float *xl, *xr, *hA, *hB, *pool, *cnt;
    int *deg;
    cudaGetSymbolAddress((void**)&xl,   g_xl);
    cudaGetSymbolAddress((void**)&xr,   g_xr);
    cudaGetSymbolAddress((void**)&hA,   g_hA);
    cudaGetSymbolAddress((void**)&hB,   g_hB);
    cudaGetSymbolAddress((void**)&pool, g_pool);
    cudaGetSymbolAddress((void**)&cnt,  g_cnt);
    cudaGetSymbolAddress((void**)&deg,  g_deg);

    const int warpGrid = (N * 32 + 255) / 256;
    const dim3 bigGrid((N + 127) / 128, 2);
    const dim3 smallGrid((N + 63) / 64, 2);

    // ---- CSR build interleaved with layer-0 GEMM (GEMM early for ncu slot) ----
    zero_i<<<(N + 255) / 256, 256>>>(deg, N);                              // 0
    prep_edges<<<(Etot + 255) / 256, 256>>>(ei, E, N);                     // 1
    scan_local<<<nb, 1024>>>(N);                                           // 2
    gemm_tc_dual<<<bigGrid, 256>>>(x, Wl[0], bl[0], xl,
                                      Wr[0], br[0], xr, N);                // 3 (ncu)
    scan_tops<<<1, 64>>>(nb);                                              // 4
    scan_add<<<(N + 255) / 256, 256>>>(N);       // also zeroes g_pos      // 5
    scatter_edges<<<(Etot + 255) / 256, 256>>>(Etot);                      // 6

    // ---- layer 0 (H=4) ----
    gat4_t<<<warpGrid, 256>>>(xl, xr, att[0], bc[0], hA, N);

    // ---- layer 1 (H=4) ----
    gemm_tc_dual<<<bigGrid, 256>>>(hA, Wl[1], bl[1], xl,
                                       Wr[1], br[1], xr, N);
    gat4_t<<<warpGrid, 256>>>(xl, xr, att[1], bc[1], hB, N);

    // ---- layer 2 (H=1) ----
    gemm128_dual<<<smallGrid, 256>>>(hB, Wl[2], bl[2], xl,
                                         Wr[2], br[2], xr, N);
    gat1<<<warpGrid, 256>>>(xl, xr, att[2], bc[2], hA, N);

    // ---- global mean pool + MLP head ----
    zero_f<<<(B * 32 + 255) / 256, 256>>>(pool, B * 32);
    zero_f<<<(B + 255) / 256, 256>>>(cnt, B);
    pool_acc<<<(N * 32 + 255) / 256, 256>>>(hA, batch, N);
    mlp_head<<<(B * 32 + 255) / 256, 256>>>(meta, Wh1, bh1, Wh2, bh2,
                                            (float*)d_out, B, metaDim);
}

// round 9
// speedup vs baseline: 3.6815x; 1.0310x over previous
#include <cuda_runtime.h>
#include <cuda_bf16.h>
#include <math.h>

// ---------------- problem-size constants (fixed dataset) ----------------
#define MAXN 50000
#define MAXE 800000
#define MAXET (MAXN + MAXE)
#define MAXB 512

// ---------------- device scratch (static, no allocation) ----------------
__device__ float g_xl[(size_t)MAXN * 128];
__device__ float g_xr[(size_t)MAXN * 128];
__device__ float g_hA[(size_t)MAXN * 128];
__device__ float g_hB[(size_t)MAXN * 128];
__device__ int   g_src[MAXET];
__device__ int   g_dst[MAXET];
__device__ int   g_deg[MAXN];
__device__ int   g_off[MAXN + 1];
__device__ int   g_pos[MAXN];
__device__ int   g_csr[MAXET];              // src ids sorted by dst
__device__ int   g_bsum[64];                // per-block sums for scan

// ---------------- helpers ----------------
__device__ __forceinline__ float warp_sum(float v) {
#pragma unroll
    for (int o = 16; o; o >>= 1) v += __shfl_xor_sync(0xffffffffu, v, o);
    return v;
}

__device__ __forceinline__ unsigned f2tf32(float f) {
    unsigned u;
    asm("cvt.rna.tf32.f32 %0, %1;" : "=r"(u) : "f"(f));
    return u;
}

__device__ __forceinline__ void mma_tf32(float* d, const unsigned* a, const unsigned* b) {
    asm volatile(
        "mma.sync.aligned.m16n8k8.row.col.f32.tf32.tf32.f32 "
        "{%0,%1,%2,%3}, {%4,%5,%6,%7}, {%8,%9}, {%0,%1,%2,%3};"
        : "+f"(d[0]), "+f"(d[1]), "+f"(d[2]), "+f"(d[3])
        : "r"(a[0]), "r"(a[1]), "r"(a[2]), "r"(a[3]), "r"(b[0]), "r"(b[1]));
}

// ---------------- small utility kernels ----------------
__global__ void zero_i(int* p, int n) {
    int i = blockIdx.x * blockDim.x + threadIdx.x;
    if (i < n) p[i] = 0;
}

// edge_index / batch are INT32 (JAX x64 disabled).
__global__ void prep_edges(const int* __restrict__ ei, int E, int N) {
    int i = blockIdx.x * blockDim.x + threadIdx.x;
    int Etot = E + N;
    if (i >= Etot) return;
    int s, d;
    if (i < E) { s = ei[i]; d = ei[E + i]; }
    else       { s = i - E; d = i - E; }
    g_src[i] = s;
    g_dst[i] = d;
    atomicAdd(&g_deg[d], 1);
}

// ---------------- multi-block scan of g_deg -> g_off ----------------
__global__ void scan_local(int N) {
    __shared__ int wsum[32];
    int b = blockIdx.x, tid = threadIdx.x, lane = tid & 31, wid = tid >> 5;
    int i = b * 1024 + tid;
    int x = (i < N) ? g_deg[i] : 0;
#pragma unroll
    for (int o = 1; o < 32; o <<= 1) {
        int y = __shfl_up_sync(0xffffffffu, x, o);
        if (lane >= o) x += y;
    }
    if (lane == 31) wsum[wid] = x;
    __syncthreads();
    if (wid == 0) {
        int s = wsum[lane];
#pragma unroll
        for (int o = 1; o < 32; o <<= 1) {
            int y = __shfl_up_sync(0xffffffffu, s, o);
            if (lane >= o) s += y;
        }
        wsum[lane] = s;
    }
    __syncthreads();
    int incl = x + (wid ? wsum[wid - 1] : 0);
    if (i < N) g_off[i + 1] = incl;
    if (tid == 1023) g_bsum[b] = incl;
}

__global__ void scan_tops(int nb) {
    __shared__ int s[64];
    int tid = threadIdx.x;
    if (tid < nb) s[tid] = g_bsum[tid];
    __syncthreads();
    if (tid == 0) {
        int a = 0;
        for (int i = 0; i < nb; i++) { int t = s[i]; s[i] = a; a += t; }
    }
    __syncthreads();
    if (tid < nb) g_bsum[tid] = s[tid];
}

__global__ void scan_add(int N) {
    int i = blockIdx.x * blockDim.x + threadIdx.x;
    if (i == 0) g_off[0] = 0;
    if (i < N) {
        g_off[i + 1] += g_bsum[i >> 10];
        g_pos[i] = 0;
    }
}

__global__ void scatter_edges(int Etot) {
    int i = blockIdx.x * blockDim.x + threadIdx.x;
    if (i >= Etot) return;
    int d = g_dst[i];
    int p = atomicAdd(&g_pos[d], 1);
    g_csr[g_off[d] + p] = g_src[i];
}

// ---------------- tf32 tensor-core dual GEMM ----------------
// {xl,xr}[N,128] = A[N,128] @ {Wl,Wr}[128,128] + bias,  blockIdx.y selects set.
__global__ __launch_bounds__(256, 2) void gemm_tc_dual(
    const float* __restrict__ A,
    const float* __restrict__ W0, const float* __restrict__ b0, float* __restrict__ C0,
    const float* __restrict__ W1, const float* __restrict__ b1, float* __restrict__ C1,
    int N)
{
    const float* W    = blockIdx.y ? W1 : W0;
    const float* bias = blockIdx.y ? b1 : b0;
    float*       C    = blockIdx.y ? C1 : C0;

    __shared__ unsigned A_s[128][36];   // [row][k within 32-chunk], pad 4
    __shared__ unsigned W_s[32][136];   // [k within chunk][col], pad 8

    const int t    = threadIdx.x;
    const int wid  = t >> 5;
    const int lane = t & 31;
    const int gid  = lane >> 2;
    const int tig  = lane & 3;
    const int wm   = wid & 3;
    const int wn   = wid >> 2;
    const int row0 = blockIdx.x * 128;

    float acc[2][8][4];
#pragma unroll
    for (int km = 0; km < 2; km++)
#pragma unroll
        for (int n = 0; n < 8; n++)
#pragma unroll
            for (int c = 0; c < 4; c++) acc[km][n][c] = 0.f;

    for (int kc = 0; kc < 4; kc++) {
#pragma unroll
        for (int i = 0; i < 4; i++) {
            int q = t + i * 256;
            int r = q >> 3, c4 = q & 7;
            float4 a4 = make_float4(0.f, 0.f, 0.f, 0.f);
            if (row0 + r < N)
                a4 = *(const float4*)&A[(size_t)(row0 + r) * 128 + kc * 32 + c4 * 4];
            uint4 ua;
            ua.x = f2tf32(a4.x); ua.y = f2tf32(a4.y);
            ua.z = f2tf32(a4.z); ua.w = f2tf32(a4.w);
            *(uint4*)&A_s[r][c4 * 4] = ua;
            int k = q >> 5, c32 = q & 31;
            float4 w4 = *(const float4*)&W[(size_t)(kc * 32 + k) * 128 + c32 * 4];
            uint4 uw;
            uw.x = f2tf32(w4.x); uw.y = f2tf32(w4.y);
            uw.z = f2tf32(w4.z); uw.w = f2tf32(w4.w);
            *(uint4*)&W_s[k][c32 * 4] = uw;
        }
        __syncthreads();

#pragma unroll
        for (int ks = 0; ks < 4; ks++) {
            const int kq = ks * 8;
            unsigned a[2][4], b[8][2];
#pragma unroll
            for (int km = 0; km < 2; km++) {
                int rb = wm * 32 + km * 16 + gid;
                a[km][0] = A_s[rb    ][kq + tig];
                a[km][1] = A_s[rb + 8][kq + tig];
                a[km][2] = A_s[rb    ][kq + tig + 4];
                a[km][3] = A_s[rb + 8][kq + tig + 4];
            }
#pragma unroll
            for (int n = 0; n < 8; n++) {
                int cb = wn * 64 + n * 8 + gid;
                b[n][0] = W_s[kq + tig    ][cb];
                b[n][1] = W_s[kq + tig + 4][cb];
            }
#pragma unroll
            for (int km = 0; km < 2; km++)
#pragma unroll
                for (int n = 0; n < 8; n++)
                    mma_tf32(acc[km][n], a[km], b[n]);
        }
        __syncthreads();
    }

#pragma unroll
    for (int km = 0; km < 2; km++) {
        int rA = row0 + wm * 32 + km * 16 + gid;
        int rB = rA + 8;
#pragma unroll
        for (int n = 0; n < 8; n++) {
            int col = wn * 64 + n * 8 + 2 * tig;
            float bx = bias[col], by = bias[col + 1];
            if (rA < N) {
                float2 o = make_float2(acc[km][n][0] + bx, acc[km][n][1] + by);
                *(float2*)&C[(size_t)rA * 128 + col] = o;
            }
            if (rB < N) {
                float2 o = make_float2(acc[km][n][2] + bx, acc[km][n][3] + by);
                *(float2*)&C[(size_t)rB * 128 + col] = o;
            }
        }
    }
}

// ---------------- dual small GEMM (M=32) ----------------
__global__ __launch_bounds__(256) void gemm128_dual(
    const float* __restrict__ A,
    const float* __restrict__ W0, const float* __restrict__ b0, float* __restrict__ C0,
    const float* __restrict__ W1, const float* __restrict__ b1, float* __restrict__ C1,
    int N)
{
    const int M = 32;
    const float* W    = blockIdx.y ? W1 : W0;
    const float* bias = blockIdx.y ? b1 : b0;
    float*       C    = blockIdx.y ? C1 : C0;

    __shared__ float As[16][64];
    __shared__ float Ws[16][64];
    const int t = threadIdx.x;
    const int row0 = blockIdx.x * 64;
    const int tx = t & 15, ty = t >> 4;

    float acc[4][4];
#pragma unroll
    for (int i = 0; i < 4; i++)
#pragma unroll
        for (int j = 0; j < 4; j++) acc[i][j] = 0.f;

    for (int k0 = 0; k0 < 128; k0 += 16) {
#pragma unroll
        for (int i = 0; i < 4; i++) {
            int idx = t + i * 256;
            int r = idx >> 4, c = idx & 15;
            int gr = row0 + r;
            As[c][r] = (gr < N) ? A[(size_t)gr * 128 + k0 + c] : 0.f;
        }
#pragma unroll
        for (int i = 0; i < 4; i++) {
            int idx = t + i * 256;
            int kk = idx >> 6, cc = idx & 63;
            Ws[kk][cc] = (cc < M) ? W[(size_t)(k0 + kk) * M + cc] : 0.f;
        }
        __syncthreads();
#pragma unroll
        for (int kk = 0; kk < 16; kk++) {
            float4 a4 = *(const float4*)&As[kk][ty * 4];
            float4 w4 = *(const float4*)&Ws[kk][tx * 4];
            float a[4] = {a4.x, a4.y, a4.z, a4.w};
            float w[4] = {w4.x, w4.y, w4.z, w4.w};
#pragma unroll
            for (int i = 0; i < 4; i++)
#pragma unroll
                for (int j = 0; j < 4; j++) acc[i][j] += a[i] * w[j];
        }
        __syncthreads();
    }
#pragma unroll
    for (int i = 0; i < 4; i++) {
        int r = row0 + ty * 4 + i;
        if (r >= N) continue;
#pragma unroll
        for (int j = 0; j < 4; j++) {
            int c = tx * 4 + j;
            if (c < M) C[(size_t)r * M + c] = acc[i][j] + bias[c];
        }
    }
}

// ---------------- transposed fused GATv2 (H=4), pair-interleaved ----------------
// Two independent online-softmax states (A: even edges, B: odd edges) break the
// per-edge dependency chain; merged exactly at the end.
__global__ void gat4_t(const float* __restrict__ xl, const float* __restrict__ xr,
                       const float* __restrict__ att, const float* __restrict__ bias,
                       float* __restrict__ out, int N)
{
    int w = (blockIdx.x * blockDim.x + threadIdx.x) >> 5;
    if (w >= N) return;
    int lane = threadIdx.x & 31;

    const float4 xrv  = *(const float4*)&xr[(size_t)w * 128 + lane * 4];
    const float4 attv = *(const float4*)&att[lane * 4];

    float  mxA = -1e30f, denA = 0.f, mxB = -1e30f, denB = 0.f;
    float4 accA = make_float4(0.f, 0.f, 0.f, 0.f);
    float4 accB = make_float4(0.f, 0.f, 0.f, 0.f);

    const int j0 = g_off[w], j1 = g_off[w + 1];
    int s0 = g_csr[j0];
    int s1 = (j0 + 1 < j1) ? g_csr[j0 + 1] : s0;
    float4 v0 = *(const float4*)&xl[(size_t)s0 * 128 + lane * 4];
    float4 v1 = *(const float4*)&xl[(size_t)s1 * 128 + lane * 4];

    for (int j = j0; j < j1; j += 2) {
        const bool has1 = (j + 1 < j1);
        // prefetch next pair
        int jn = j + 2;
        int sn0 = (jn < j1) ? g_csr[jn] : s0;
        int sn1 = (jn + 1 < j1) ? g_csr[jn + 1] : sn0;
        float4 vn0 = *(const float4*)&xl[(size_t)sn0 * 128 + lane * 4];
        float4 vn1 = *(const float4*)&xl[(size_t)sn1 * 128 + lane * 4];

        // logits for both edges (chains interleave in the scheduler)
        float a0 = v0.x + xrv.x; a0 = fmaxf(a0, 0.2f * a0);
        float a1 = v0.y + xrv.y; a1 = fmaxf(a1, 0.2f * a1);
        float a2 = v0.z + xrv.z; a2 = fmaxf(a2, 0.2f * a2);
        float a3 = v0.w + xrv.w; a3 = fmaxf(a3, 0.2f * a3);
        float p0 = a0 * attv.x + a1 * attv.y + a2 * attv.z + a3 * attv.w;

        float b0 = v1.x + xrv.x; b0 = fmaxf(b0, 0.2f * b0);
        float b1 = v1.y + xrv.y; b1 = fmaxf(b1, 0.2f * b1);
        float b2 = v1.z + xrv.z; b2 = fmaxf(b2, 0.2f * b2);
        float b3 = v1.w + xrv.w; b3 = fmaxf(b3, 0.2f * b3);
        float p1 = b0 * attv.x + b1 * attv.y + b2 * attv.z + b3 * attv.w;

        p0 += __shfl_xor_sync(0xffffffffu, p0, 1);
        p1 += __shfl_xor_sync(0xffffffffu, p1, 1);
        p0 += __shfl_xor_sync(0xffffffffu, p0, 2);
        p1 += __shfl_xor_sync(0xffffffffu, p1, 2);
        p0 += __shfl_xor_sync(0xffffffffu, p0, 4);
        p1 += __shfl_xor_sync(0xffffffffu, p1, 4);

        // chain A update (even edge)
        {
            float nm = fmaxf(mxA, p0);
            float sc = __expf(mxA - nm);
            float e  = __expf(p0 - nm);
            mxA = nm;
            denA = denA * sc + e;
            accA.x = accA.x * sc + e * v0.x;
            accA.y = accA.y * sc + e * v0.y;
            accA.z = accA.z * sc + e * v0.z;
            accA.w = accA.w * sc + e * v0.w;
        }
        // chain B update (odd edge)
        if (has1) {
            float nm = fmaxf(mxB, p1);
            float sc = __expf(mxB - nm);
            float e  = __expf(p1 - nm);
            mxB = nm;
            denB = denB * sc + e;
            accB.x = accB.x * sc + e * v1.x;
            accB.y = accB.y * sc + e * v1.y;
            accB.z = accB.z * sc + e * v1.z;
            accB.w = accB.w * sc + e * v1.w;
        }
        v0 = vn0; v1 = vn1;
    }

    // merge chains
    float nm = fmaxf(mxA, mxB);
    float sA = __expf(mxA - nm), sB = __expf(mxB - nm);
    float den = denA * sA + denB * sB;
    float4 acc;
    acc.x = accA.x * sA + accB.x * sB;
    acc.y = accA.y * sA + accB.y * sB;
    acc.z = accA.z * sA + accB.z * sB;
    acc.w = accA.w * sA + accB.w * sB;

    float inv = 1.f / (den + 1e-16f);
    float4 bv = *(const float4*)&bias[lane * 4];
    float4 o;
    o.x = acc.x * inv + bv.x; o.x = o.x > 0.f ? o.x : expm1f(o.x);
    o.y = acc.y * inv + bv.y; o.y = o.y > 0.f ? o.y : expm1f(o.y);
    o.z = acc.z * inv + bv.z; o.z = o.z > 0.f ? o.z : expm1f(o.z);
    o.w = acc.w * inv + bv.w; o.w = o.w > 0.f ? o.w : expm1f(o.w);
    *(float4*)&out[(size_t)w * 128 + lane * 4] = o;
}

// ---------------- fused GATv2 (H=1), pair-interleaved ----------------
__global__ void gat1(const float* __restrict__ xl, const float* __restrict__ xr,
                     const float* __restrict__ att, const float* __restrict__ bias,
                     float* __restrict__ out, int N)
{
    int w = (blockIdx.x * blockDim.x + threadIdx.x) >> 5;
    if (w >= N) return;
    int lane = threadIdx.x & 31;

    float xrv  = xr[(size_t)w * 32 + lane];
    float attv = att[lane];
    float mxA = -1e30f, denA = 0.f, accA = 0.f;
    float mxB = -1e30f, denB = 0.f, accB = 0.f;

    const int j0 = g_off[w], j1 = g_off[w + 1];
    int s0 = g_csr[j0];
    int s1 = (j0 + 1 < j1) ? g_csr[j0 + 1] : s0;
    float v0 = xl[(size_t)s0 * 32 + lane];
    float v1 = xl[(size_t)s1 * 32 + lane];

    for (int j = j0; j < j1; j += 2) {
        const bool has1 = (j + 1 < j1);
        int jn = j + 2;
        int sn0 = (jn < j1) ? g_csr[jn] : s0;
        int sn1 = (jn + 1 < j1) ? g_csr[jn + 1] : sn0;
        float vn0 = xl[(size_t)sn0 * 32 + lane];
        float vn1 = xl[(size_t)sn1 * 32 + lane];

        float t0 = v0 + xrv; t0 = fmaxf(t0, 0.2f * t0);
        float t1 = v1 + xrv; t1 = fmaxf(t1, 0.2f * t1);
        float p0 = t0 * attv, p1 = t1 * attv;
#pragma unroll
        for (int o = 16; o; o >>= 1) {
            p0 += __shfl_xor_sync(0xffffffffu, p0, o);
            p1 += __shfl_xor_sync(0xffffffffu, p1, o);
        }

        {
            float nm = fmaxf(mxA, p0);
            float sc = __expf(mxA - nm);
            float e  = __expf(p0 - nm);
            mxA = nm; denA = denA * sc + e; accA = accA * sc + e * v0;
        }
        if (has1) {
            float nm = fmaxf(mxB, p1);
            float sc = __expf(mxB - nm);
            float e  = __expf(p1 - nm);
            mxB = nm; denB = denB * sc + e; accB = accB * sc + e * v1;
        }
        v0 = vn0; v1 = vn1;
    }

    float nm = fmaxf(mxA, mxB);
    float sA = __expf(mxA - nm), sB = __expf(mxB - nm);
    float den = denA * sA + denB * sB;
    float acc = accA * sA + accB * sB;

    float o = acc / (den + 1e-16f) + bias[lane];
    o = o > 0.f ? o : expm1f(o);
    out[(size_t)w * 32 + lane] = o;
}

// ---------------- fused mean-pool + MLP head: one warp per graph ----------------
// batch is sorted, so each graph's nodes are a contiguous range: binary search.
__global__ void pool_head(const float* __restrict__ h, const int* __restrict__ batch,
                          const float* __restrict__ meta,
                          const float* __restrict__ Wh1, const float* __restrict__ bh1,
                          const float* __restrict__ Wh2, const float* __restrict__ bh2,
                          float* __restrict__ out, int N, int B, int metaDim)
{
    int g = (blockIdx.x * blockDim.x + threadIdx.x) >> 5;
    int lane = threadIdx.x & 31;
    if (g >= B) return;

    // lower_bound(batch, g) and lower_bound(batch, g+1)
    int lo = 0, hi = N;
    while (lo < hi) { int m = (lo + hi) >> 1; if (batch[m] < g) lo = m + 1; else hi = m; }
    int start = lo;
    hi = N;
    while (lo < hi) { int m = (lo + hi) >> 1; if (batch[m] < g + 1) lo = m + 1; else hi = m; }
    int end = lo;

    float sum = 0.f;
    int i = start;
    for (; i + 4 <= end; i += 4) {
        float x0 = h[(size_t)(i + 0) * 32 + lane];
        float x1 = h[(size_t)(i + 1) * 32 + lane];
        float x2 = h[(size_t)(i + 2) * 32 + lane];
        float x3 = h[(size_t)(i + 3) * 32 + lane];
        sum += (x0 + x1) + (x2 + x3);
    }
    for (; i < end; i++) sum += h[(size_t)i * 32 + lane];

    float cnt = fmaxf((float)(end - start), 1.f);
    float emb = sum / cnt;                           // channel=lane of graph embedding

    float acc = bh1[lane];
#pragma unroll
    for (int k = 0; k < 32; k++)
        acc += __shfl_sync(0xffffffffu, emb, k) * Wh1[k * 32 + lane];
    for (int k = 0; k < metaDim; k++)
        acc += meta[(size_t)g * metaDim + k] * Wh1[(32 + k) * 32 + lane];
    acc = fmaxf(acc, 0.f);
    float p = warp_sum(acc * Wh2[lane]);
    if (lane == 0) out[g] = p + bh2[0];
}

// ---------------- host launcher ----------------
extern "C" void kernel_launch(void* const* d_in, const int* in_sizes, int n_in,
                              void* d_out, int out_size)
{
    const float* x     = (const float*)d_in[0];
    const int*   ei    = (const int*)d_in[1];    // int32 (JAX x64 disabled)
    const int*   batch = (const int*)d_in[2];    // int32
    const float* meta  = (const float*)d_in[3];
    const float* Wl[3]  = {(const float*)d_in[4],  (const float*)d_in[10], (const float*)d_in[16]};
    const float* bl[3]  = {(const float*)d_in[5],  (const float*)d_in[11], (const float*)d_in[17]};
    const float* Wr[3]  = {(const float*)d_in[6],  (const float*)d_in[12], (const float*)d_in[18]};
    const float* br[3]  = {(const float*)d_in[7],  (const float*)d_in[13], (const float*)d_in[19]};
    const float* att[3] = {(const float*)d_in[8],  (const float*)d_in[14], (const float*)d_in[20]};
    const float* bc[3]  = {(const float*)d_in[9],  (const float*)d_in[15], (const float*)d_in[21]};
    const float* Wh1 = (const float*)d_in[22];
    const float* bh1 = (const float*)d_in[23];
    const float* Wh2 = (const float*)d_in[24];
    const float* bh2 = (const float*)d_in[25];

    const int N = in_sizes[0] / 128;
    const int E = in_sizes[1] / 2;
    const int metaDim = 12;
    const int B = in_sizes[3] / metaDim;
    const int Etot = E + N;
    const int nb = (N + 1023) / 1024;

    float *xl, *xr, *hA, *hB;
    int *deg;
    cudaGetSymbolAddress((void**)&xl, g_xl);
    cudaGetSymbolAddress((void**)&xr, g_xr);
    cudaGetSymbolAddress((void**)&hA, g_hA);
    cudaGetSymbolAddress((void**)&hB, g_hB);
    cudaGetSymbolAddress((void**)&deg, g_deg);

    const int warpGrid = (N * 32 + 255) / 256;
    const dim3 bigGrid((N + 127) / 128, 2);
    const dim3 smallGrid((N + 63) / 64, 2);

    // ---- CSR build interleaved with layer-0 GEMM ----
    zero_i<<<(N + 255) / 256, 256>>>(deg, N);
    prep_edges<<<(Etot + 255) / 256, 256>>>(ei, E, N);
    scan_local<<<nb, 1024>>>(N);
    gemm_tc_dual<<<bigGrid, 256>>>(x, Wl[0], bl[0], xl,
                                      Wr[0], br[0], xr, N);
    scan_tops<<<1, 64>>>(nb);
    scan_add<<<(N + 255) / 256, 256>>>(N);       // also zeroes g_pos
    scatter_edges<<<(Etot + 255) / 256, 256>>>(Etot);

    // ---- layer 0 (H=4) ----
    gat4_t<<<warpGrid, 256>>>(xl, xr, att[0], bc[0], hA, N);

    // ---- layer 1 (H=4) ----
    gemm_tc_dual<<<bigGrid, 256>>>(hA, Wl[1], bl[1], xl,
                                       Wr[1], br[1], xr, N);
    gat4_t<<<warpGrid, 256>>>(xl, xr, att[1], bc[1], hB, N);

    // ---- layer 2 (H=1) ----
    gemm128_dual<<<smallGrid, 256>>>(hB, Wl[2], bl[2], xl,
                                         Wr[2], br[2], xr, N);
    gat1<<<warpGrid, 256>>>(xl, xr, att[2], bc[2], hA, N);

    // ---- fused mean pool + MLP head ----
    pool_head<<<(B * 32 + 255) / 256, 256>>>(hA, batch, meta, Wh1, bh1, Wh2, bh2,
                                             (float*)d_out, N, B, metaDim);
}